// round 14
// baseline (speedup 1.0000x reference)
#include <cuda_runtime.h>
#include <cuda_bf16.h>
#include <cstdint>

// Problem constants (fixed for this dataset instance)
#define EMAX 1000000
#define DDIM 128
#define NMAX 200000
#define BMAX 512
#define NRMAX 481      // 2R+1
#define TMAX 100000

// ---------------- device scratch (static globals; no allocation) ----------------
__device__ uint32_t g_U16[NMAX * 64];     // hidden @ Ws, bf16 packed (2 per uint)
__device__ uint32_t g_Vr16[NRMAX * 64];   // rel_table @ Wr, bf16 packed
__device__ uint32_t g_Qb16[BMAX * 64];    // (rel_table[query_rel+1] @ Wqr_w + b), bf16 packed
__device__ float g_AGG[TMAX * DDIM];      // segment sums
__device__ float g_alphaE[EMAX];          // per-edge gate, indexed by edge id
// tail sort
__device__ int   g_segcnt[TMAX];
__device__ int   g_segstart[TMAX + 1];
__device__ int   g_cursor[TMAX];
__device__ int   g_part[256];
__device__ int2  g_aggRec2[EMAX];         // tail-sorted: (n | (r+1)<<18, edge_id)
// node sort (independent of tail sort)
__device__ int   g_ncnt[NMAX];
__device__ int   g_nstart[NMAX + 1];
__device__ int   g_ncursor[NMAX];
__device__ int   g_partN[256];
__device__ int2  g_eRec[EMAX];            // n-sorted: (b | (r+1)<<9, edge_id)
// pre-split transposed weight images Wt[n][k] (bf16 hi/lo, packed as uint32 = 2 halves)
__device__ uint32_t g_WsHi[8192];
__device__ uint32_t g_WsLo[8192];
__device__ uint32_t g_WhHi[8192];
__device__ uint32_t g_WhLo[8192];

__device__ __forceinline__ uint32_t smem_u32(const void* p) {
    uint32_t a;
    asm("{ .reg .u64 t; cvta.to.shared.u64 t, %1; cvt.u32.u64 %0, t; }" : "=r"(a) : "l"(p));
    return a;
}
__device__ __forceinline__ uint32_t b2u(__nv_bfloat162 h) { return *reinterpret_cast<uint32_t*>(&h); }
__device__ __forceinline__ float2 u2f2(uint32_t u) {
    return __bfloat1622float2(*reinterpret_cast<__nv_bfloat162*>(&u));
}

__device__ __forceinline__ void ldsm_x4(uint32_t addr, uint32_t& r0, uint32_t& r1,
                                        uint32_t& r2, uint32_t& r3) {
    asm volatile("ldmatrix.sync.aligned.m8n8.x4.shared.b16 {%0,%1,%2,%3}, [%4];"
                 : "=r"(r0), "=r"(r1), "=r"(r2), "=r"(r3) : "r"(addr));
}
__device__ __forceinline__ void mma16816(float* d, const uint32_t* a, const uint32_t* b) {
    asm volatile(
        "mma.sync.aligned.m16n8k16.row.col.f32.bf16.bf16.f32 "
        "{%0,%1,%2,%3}, {%4,%5,%6,%7}, {%8,%9}, {%0,%1,%2,%3};"
        : "+f"(d[0]), "+f"(d[1]), "+f"(d[2]), "+f"(d[3])
        : "r"(a[0]), "r"(a[1]), "r"(a[2]), "r"(a[3]), "r"(b[0]), "r"(b[1]));
}

// ---------------- generic helpers ----------------
__global__ void k_zero(int* __restrict__ p, int n) {
    int i = blockIdx.x * blockDim.x + threadIdx.x;
    if (i < n) p[i] = 0;
}

// ---------------- tail sort kernels ----------------
__global__ void k_hist_tail(const int* __restrict__ tail, int E) {
    int e = blockIdx.x * blockDim.x + threadIdx.x;
    if (e < E) atomicAdd(&g_segcnt[tail[e]], 1);
}

__global__ void k_hist_n(const int* __restrict__ facts, int E) {
    int e = blockIdx.x * blockDim.x + threadIdx.x;
    if (e < E) {
        int2 bn = *(const int2*)(facts + e * 6);
        atomicAdd(&g_ncnt[bn.y], 1);
    }
}

__global__ void k_scanA(const int* __restrict__ cnt, int* __restrict__ start,
                        int* __restrict__ part, int T) {
    __shared__ int s[1024];
    int i = blockIdx.x * 1024 + threadIdx.x;
    int v = (i < T) ? cnt[i] : 0;
    s[threadIdx.x] = v;
    __syncthreads();
    for (int off = 1; off < 1024; off <<= 1) {
        int x = (threadIdx.x >= off) ? s[threadIdx.x - off] : 0;
        __syncthreads();
        s[threadIdx.x] += x;
        __syncthreads();
    }
    if (i < T) start[i] = s[threadIdx.x] - v;  // block-local exclusive
    if (threadIdx.x == 1023) part[blockIdx.x] = s[1023];
}

__global__ void k_scanB(int* __restrict__ part, int nb) {
    __shared__ int s[256];
    int i = threadIdx.x;
    int v = (i < nb) ? part[i] : 0;
    s[i] = v;
    __syncthreads();
    for (int off = 1; off < 256; off <<= 1) {
        int x = (i >= off) ? s[i - off] : 0;
        __syncthreads();
        s[i] += x;
        __syncthreads();
    }
    if (i < nb) part[i] = s[i] - v;  // exclusive
}

__global__ void k_scanC(int* __restrict__ start, int* __restrict__ cursor,
                        const int* __restrict__ part, int T, int E) {
    int i = blockIdx.x * 1024 + threadIdx.x;
    if (i < T) {
        int v = start[i] + part[blockIdx.x];
        start[i] = v;
        cursor[i] = v;
    }
    if (i == 0) start[T] = E;
}

// tail scatter: (n | (r+1)<<18, edge_id) at the sorted position
__global__ void k_scatter_tail(const int* __restrict__ tail, const int* __restrict__ facts, int E) {
    int e = blockIdx.x * blockDim.x + threadIdx.x;
    if (e < E) {
        int2 bn = *(const int2*)(facts + e * 6);      // (b, n)
        int2 hr = *(const int2*)(facts + e * 6 + 2);  // (h, r)
        int p = atomicAdd(&g_cursor[tail[e]], 1);
        g_aggRec2[p] = make_int2(bn.y | ((hr.y + 1) << 18), e);
    }
}

// node scatter: (b | (r+1)<<9, edge_id) at the n-sorted position (independent of tail sort)
__global__ void k_scatter_n(const int* __restrict__ facts, int E) {
    int e = blockIdx.x * blockDim.x + threadIdx.x;
    if (e < E) {
        int2 bn = *(const int2*)(facts + e * 6);      // (b, n)
        int2 hr = *(const int2*)(facts + e * 6 + 2);  // (h, r)
        int q = atomicAdd(&g_ncursor[bn.y], 1);
        g_eRec[q] = make_int2(bn.x | ((hr.y + 1) << 9), e);
    }
}

// ---------------- fused tiny projections (bf16 output): blocks [0,NR) -> Vr16, [NR,NR+B) -> Qb16
__global__ void k_vrqb(const float* __restrict__ rel, const float* __restrict__ Wr,
                       const float* __restrict__ Wq, const float* __restrict__ bias,
                       const int* __restrict__ qrel, int NR) {
    __shared__ float row[DDIM];
    __shared__ float val[DDIM];
    int j = threadIdx.x;
    if ((int)blockIdx.x < NR) {
        int r = blockIdx.x;
        row[j] = rel[r * DDIM + j];
        __syncthreads();
        float s = 0.f;
        #pragma unroll 8
        for (int k = 0; k < DDIM; k++) s = fmaf(row[k], Wr[k * DDIM + j], s);
        val[j] = s;
        __syncthreads();
        if (j < 64) g_Vr16[r * 64 + j] = b2u(__floats2bfloat162_rn(val[2 * j], val[2 * j + 1]));
    } else {
        int b = blockIdx.x - NR;
        int r = qrel[b] + 1;
        row[j] = rel[r * DDIM + j];
        __syncthreads();
        float s = bias[j];
        #pragma unroll 8
        for (int k = 0; k < DDIM; k++) s = fmaf(row[k], Wq[k * DDIM + j], s);
        val[j] = s;
        __syncthreads();
        if (j < 64) g_Qb16[b * 64 + j] = b2u(__floats2bfloat162_rn(val[2 * j], val[2 * j + 1]));
    }
}

// ---------------- weight prep: both weights in one launch (block 0: Ws, block 1: Wh) ----------------
__global__ void k_prep_w2(const float* __restrict__ Ws, const float* __restrict__ Wh) {
    const float* W = (blockIdx.x == 0) ? Ws : Wh;
    uint32_t* outHi = (blockIdx.x == 0) ? g_WsHi : g_WhHi;
    uint32_t* outLo = (blockIdx.x == 0) ? g_WsLo : g_WhLo;
    int n = threadIdx.x;
    #pragma unroll 4
    for (int k = 0; k < 128; k += 2) {
        float w0 = W[(k + 0) * 128 + n];
        float w1 = W[(k + 1) * 128 + n];
        __nv_bfloat162 hi = __floats2bfloat162_rn(w0, w1);
        float l0 = w0 - __bfloat162float(hi.x);
        float l1 = w1 - __bfloat162float(hi.y);
        __nv_bfloat162 lo = __floats2bfloat162_rn(l0, l1);
        outHi[n * 64 + (k >> 1)] = b2u(hi);
        outLo[n * 64 + (k >> 1)] = b2u(lo);
    }
}

#define BSTRIDE 136                       // halves per smem row (272B -> conflict-free ldmatrix)

// ---------------- plain-bf16 GEMM (gate path): U16[M,128] = bf16(A[M,128] @ Ws) ----------------
#define SMEM_G1 (192 * BSTRIDE * 2)       // 52224B -> 4 CTAs/SM

__global__ __launch_bounds__(256)
void gemm_bf16(const float* __restrict__ A, const uint32_t* __restrict__ BHi,
               uint32_t* __restrict__ C16, int M) {
    extern __shared__ __align__(16) uint8_t smraw[];
    __nv_bfloat16* sAhi = (__nv_bfloat16*)smraw;
    __nv_bfloat16* sBhi = sAhi + 64 * BSTRIDE;

    const int tid = threadIdx.x;
    const int w = tid >> 5, lane = tid & 31;
    const int rbase = blockIdx.x * 64;

    const uint4* bh4 = (const uint4*)BHi;
    #pragma unroll
    for (int it = 0; it < 8; it++) {
        int i = it * 256 + tid;
        int n = i >> 4, c = i & 15;
        *(uint4*)(sBhi + n * BSTRIDE + c * 8) = bh4[i];
    }
    const float4* A4 = (const float4*)A;
    #pragma unroll
    for (int it = 0; it < 8; it++) {
        int f = it * 256 + tid;           // 0..2047
        int row = f >> 5, c4 = f & 31;
        int gr = rbase + row;
        float4 v = make_float4(0.f, 0.f, 0.f, 0.f);
        if (gr < M) v = A4[gr * 32 + c4];
        __nv_bfloat162 h01 = __floats2bfloat162_rn(v.x, v.y);
        __nv_bfloat162 h23 = __floats2bfloat162_rn(v.z, v.w);
        *(uint2*)(sAhi + row * BSTRIDE + c4 * 4) = make_uint2(b2u(h01), b2u(h23));
    }
    __syncthreads();

    const int wm = w >> 2, wn = w & 3;
    const int quad = lane >> 3, l = lane & 7;
    const uint32_t aoff0 = (uint32_t)(((wm * 32 + 0  + (quad & 1) * 8 + l) * BSTRIDE + (quad >> 1) * 8) * 2);
    const uint32_t aoff1 = (uint32_t)(((wm * 32 + 16 + (quad & 1) * 8 + l) * BSTRIDE + (quad >> 1) * 8) * 2);
    const uint32_t boff0 = (uint32_t)(((wn * 32 + 0  + (quad >> 1) * 8 + l) * BSTRIDE + (quad & 1) * 8) * 2);
    const uint32_t boff1 = (uint32_t)(((wn * 32 + 16 + (quad >> 1) * 8 + l) * BSTRIDE + (quad & 1) * 8) * 2);
    const uint32_t aHi0 = smem_u32(sAhi) + aoff0, aHi1 = smem_u32(sAhi) + aoff1;
    const uint32_t bHi0 = smem_u32(sBhi) + boff0, bHi1 = smem_u32(sBhi) + boff1;

    float acc[2][4][4];
    #pragma unroll
    for (int i = 0; i < 2; i++)
        #pragma unroll
        for (int j = 0; j < 4; j++)
            #pragma unroll
            for (int q = 0; q < 4; q++) acc[i][j][q] = 0.f;

    #pragma unroll 4
    for (int ks = 0; ks < 8; ks++) {
        const uint32_t ko = (uint32_t)(ks * 32);
        uint32_t ah0[4], ah1[4], bh0[4], bh1[4];
        ldsm_x4(aHi0 + ko, ah0[0], ah0[1], ah0[2], ah0[3]);
        ldsm_x4(aHi1 + ko, ah1[0], ah1[1], ah1[2], ah1[3]);
        ldsm_x4(bHi0 + ko, bh0[0], bh0[1], bh0[2], bh0[3]);
        ldsm_x4(bHi1 + ko, bh1[0], bh1[1], bh1[2], bh1[3]);
        mma16816(acc[0][0], ah0, bh0); mma16816(acc[0][1], ah0, bh0 + 2);
        mma16816(acc[0][2], ah0, bh1); mma16816(acc[0][3], ah0, bh1 + 2);
        mma16816(acc[1][0], ah1, bh0); mma16816(acc[1][1], ah1, bh0 + 2);
        mma16816(acc[1][2], ah1, bh1); mma16816(acc[1][3], ah1, bh1 + 2);
    }

    // epilogue: stage packed bf16 pairs in smem (reuse A tile), then coalesced stores
    __syncthreads();
    uint32_t* stage = (uint32_t*)smraw;   // stride 68 uint32 per row (conflict-free)
    #pragma unroll
    for (int i = 0; i < 2; i++) {
        const int rloc = wm * 32 + i * 16 + (lane >> 2);
        #pragma unroll
        for (int jn = 0; jn < 4; jn++) {
            const int cn = wn * 32 + jn * 8 + (lane & 3) * 2;  // even
            stage[rloc * 68 + (cn >> 1)]       = b2u(__floats2bfloat162_rn(acc[i][jn][0], acc[i][jn][1]));
            stage[(rloc + 8) * 68 + (cn >> 1)] = b2u(__floats2bfloat162_rn(acc[i][jn][2], acc[i][jn][3]));
        }
    }
    __syncthreads();
    const uint2* st2 = (const uint2*)stage;   // row stride 34 uint2
    uint2* C2 = (uint2*)C16;                  // row stride 32 uint2
    #pragma unroll
    for (int it = 0; it < 8; it++) {
        int idx = it * 256 + tid;             // 0..2047
        int row = idx >> 5, c2 = idx & 31;
        int gr = rbase + row;
        if (gr < M) C2[gr * 32 + c2] = st2[row * 34 + c2];
    }
}

// ---------------- bf16x3 GEMM (output path): C[M,128] = A[M,128] @ Wh ----------------
#define SOFF_ALO (64 * BSTRIDE)
#define SOFF_BHI (128 * BSTRIDE)
#define SOFF_BLO (256 * BSTRIDE)
#define SMEM_G3 (384 * BSTRIDE * 2)       // 104448 bytes

__global__ __launch_bounds__(256, 2)
void gemm_mma(const float* __restrict__ A, const uint32_t* __restrict__ BHi,
              const uint32_t* __restrict__ BLo, float* __restrict__ C, int M) {
    extern __shared__ __align__(16) uint8_t smraw[];
    __nv_bfloat16* sAhi = (__nv_bfloat16*)smraw;
    __nv_bfloat16* sAlo = sAhi + SOFF_ALO;
    __nv_bfloat16* sBhi = sAhi + SOFF_BHI;
    __nv_bfloat16* sBlo = sAhi + SOFF_BLO;

    const int tid = threadIdx.x;
    const int w = tid >> 5, lane = tid & 31;
    const int rbase = blockIdx.x * 64;

    const uint4* bh4 = (const uint4*)BHi;
    const uint4* bl4 = (const uint4*)BLo;
    #pragma unroll
    for (int it = 0; it < 16; it++) {
        int i = it * 256 + tid;           // 0..4095
        int j = i & 2047;
        int n = j >> 4, c = j & 15;
        __nv_bfloat16* dst = (i < 2048) ? sBhi : sBlo;
        *(uint4*)(dst + n * BSTRIDE + c * 8) = (i < 2048) ? bh4[j] : bl4[j];
    }
    const float4* A4 = (const float4*)A;
    #pragma unroll
    for (int it = 0; it < 8; it++) {
        int f = it * 256 + tid;           // 0..2047
        int row = f >> 5, c4 = f & 31;
        int gr = rbase + row;
        float4 v = make_float4(0.f, 0.f, 0.f, 0.f);
        if (gr < M) v = A4[gr * 32 + c4];
        __nv_bfloat162 h01 = __floats2bfloat162_rn(v.x, v.y);
        __nv_bfloat162 h23 = __floats2bfloat162_rn(v.z, v.w);
        __nv_bfloat162 l01 = __floats2bfloat162_rn(v.x - __bfloat162float(h01.x),
                                                   v.y - __bfloat162float(h01.y));
        __nv_bfloat162 l23 = __floats2bfloat162_rn(v.z - __bfloat162float(h23.x),
                                                   v.w - __bfloat162float(h23.y));
        *(uint2*)(sAhi + row * BSTRIDE + c4 * 4) = make_uint2(b2u(h01), b2u(h23));
        *(uint2*)(sAlo + row * BSTRIDE + c4 * 4) = make_uint2(b2u(l01), b2u(l23));
    }
    __syncthreads();

    const int wm = w >> 2, wn = w & 3;
    const int quad = lane >> 3, l = lane & 7;
    const uint32_t aoff0 = (uint32_t)(((wm * 32 + 0  + (quad & 1) * 8 + l) * BSTRIDE + (quad >> 1) * 8) * 2);
    const uint32_t aoff1 = (uint32_t)(((wm * 32 + 16 + (quad & 1) * 8 + l) * BSTRIDE + (quad >> 1) * 8) * 2);
    const uint32_t boff0 = (uint32_t)(((wn * 32 + 0  + (quad >> 1) * 8 + l) * BSTRIDE + (quad & 1) * 8) * 2);
    const uint32_t boff1 = (uint32_t)(((wn * 32 + 16 + (quad >> 1) * 8 + l) * BSTRIDE + (quad & 1) * 8) * 2);
    const uint32_t sA = smem_u32(sAhi), sAl = smem_u32(sAlo);
    const uint32_t sB = smem_u32(sBhi), sBl = smem_u32(sBlo);
    const uint32_t aHi0 = sA + aoff0, aHi1 = sA + aoff1;
    const uint32_t aLo0 = sAl + aoff0, aLo1 = sAl + aoff1;
    const uint32_t bHi0 = sB + boff0, bHi1 = sB + boff1;
    const uint32_t bLo0 = sBl + boff0, bLo1 = sBl + boff1;

    float acc[2][4][4];
    #pragma unroll
    for (int i = 0; i < 2; i++)
        #pragma unroll
        for (int j = 0; j < 4; j++)
            #pragma unroll
            for (int q = 0; q < 4; q++) acc[i][j][q] = 0.f;

    #pragma unroll 1
    for (int ks = 0; ks < 8; ks++) {
        const uint32_t ko = (uint32_t)(ks * 32);
        uint32_t ah0[4], ah1[4], al0[4], al1[4];
        uint32_t bh0[4], bh1[4], bl0[4], bl1[4];
        ldsm_x4(aHi0 + ko, ah0[0], ah0[1], ah0[2], ah0[3]);
        ldsm_x4(aHi1 + ko, ah1[0], ah1[1], ah1[2], ah1[3]);
        ldsm_x4(bHi0 + ko, bh0[0], bh0[1], bh0[2], bh0[3]);
        ldsm_x4(bHi1 + ko, bh1[0], bh1[1], bh1[2], bh1[3]);
        ldsm_x4(aLo0 + ko, al0[0], al0[1], al0[2], al0[3]);
        ldsm_x4(aLo1 + ko, al1[0], al1[1], al1[2], al1[3]);
        ldsm_x4(bLo0 + ko, bl0[0], bl0[1], bl0[2], bl0[3]);
        ldsm_x4(bLo1 + ko, bl1[0], bl1[1], bl1[2], bl1[3]);

        mma16816(acc[0][0], ah0, bh0); mma16816(acc[0][1], ah0, bh0 + 2);
        mma16816(acc[0][2], ah0, bh1); mma16816(acc[0][3], ah0, bh1 + 2);
        mma16816(acc[1][0], ah1, bh0); mma16816(acc[1][1], ah1, bh0 + 2);
        mma16816(acc[1][2], ah1, bh1); mma16816(acc[1][3], ah1, bh1 + 2);

        mma16816(acc[0][0], ah0, bl0); mma16816(acc[0][1], ah0, bl0 + 2);
        mma16816(acc[0][2], ah0, bl1); mma16816(acc[0][3], ah0, bl1 + 2);
        mma16816(acc[1][0], ah1, bl0); mma16816(acc[1][1], ah1, bl0 + 2);
        mma16816(acc[1][2], ah1, bl1); mma16816(acc[1][3], ah1, bl1 + 2);

        mma16816(acc[0][0], al0, bh0); mma16816(acc[0][1], al0, bh0 + 2);
        mma16816(acc[0][2], al0, bh1); mma16816(acc[0][3], al0, bh1 + 2);
        mma16816(acc[1][0], al1, bh0); mma16816(acc[1][1], al1, bh0 + 2);
        mma16816(acc[1][2], al1, bh1); mma16816(acc[1][3], al1, bh1 + 2);
    }

    // epilogue: direct float2 stores (measured faster than smem staging here)
    #pragma unroll
    for (int i = 0; i < 2; i++) {
        const int r0 = rbase + wm * 32 + i * 16 + (lane >> 2);
        #pragma unroll
        for (int jn = 0; jn < 4; jn++) {
            const int cn = wn * 32 + jn * 8 + (lane & 3) * 2;
            if (r0 < M)     *(float2*)&C[r0 * 128 + cn]       = make_float2(acc[i][jn][0], acc[i][jn][1]);
            if (r0 + 8 < M) *(float2*)&C[(r0 + 8) * 128 + cn] = make_float2(acc[i][jn][2], acc[i][jn][3]);
        }
    }
}

// ---------------- node-ordered gate: warp per node, U16[n] loaded once ----------------
// alpha = sigmoid(wa . relu(U16[n]+Vr16[r]+Qb16[b]) + wa_b) -> g_alphaE[edge_id]
__global__ __launch_bounds__(256)
void k_alpha(const float* __restrict__ wa_w, const float* __restrict__ wa_b, int N) {
    int node = (blockIdx.x * blockDim.x + threadIdx.x) >> 5;
    int lane = threadIdx.x & 31;
    if (node >= N) return;
    int s0 = g_nstart[node];
    int s1 = g_nstart[node + 1];
    if (s0 == s1) return;

    const uint2* U2 = (const uint2*)g_U16;
    const uint2* V2 = (const uint2*)g_Vr16;
    const uint2* Q2 = (const uint2*)g_Qb16;

    uint2 u = U2[node * 32 + lane];
    float2 u0 = u2f2(u.x), u1 = u2f2(u.y);
    float4 w = ((const float4*)wa_w)[lane];
    float wb = wa_b[0];

    int k = s0;
    for (; k + 1 < s1; k += 2) {
        int2 rA = g_eRec[k];
        int2 rB = g_eRec[k + 1];
        int bA = rA.x & 511, rrA = rA.x >> 9;
        int bB = rB.x & 511, rrB = rB.x >> 9;
        uint2 vA = V2[rrA * 32 + lane], vB = V2[rrB * 32 + lane];
        uint2 qA = Q2[bA * 32 + lane],  qB = Q2[bB * 32 + lane];
        float2 va0 = u2f2(vA.x), va1 = u2f2(vA.y);
        float2 qa0 = u2f2(qA.x), qa1 = u2f2(qA.y);
        float sA = fmaxf(u0.x + va0.x + qa0.x, 0.f) * w.x
                 + fmaxf(u0.y + va0.y + qa0.y, 0.f) * w.y
                 + fmaxf(u1.x + va1.x + qa1.x, 0.f) * w.z
                 + fmaxf(u1.y + va1.y + qa1.y, 0.f) * w.w;
        float2 vb0 = u2f2(vB.x), vb1 = u2f2(vB.y);
        float2 qb0 = u2f2(qB.x), qb1 = u2f2(qB.y);
        float sB = fmaxf(u0.x + vb0.x + qb0.x, 0.f) * w.x
                 + fmaxf(u0.y + vb0.y + qb0.y, 0.f) * w.y
                 + fmaxf(u1.x + vb1.x + qb1.x, 0.f) * w.z
                 + fmaxf(u1.y + vb1.y + qb1.y, 0.f) * w.w;
        #pragma unroll
        for (int o = 16; o > 0; o >>= 1) {
            sA += __shfl_xor_sync(0xffffffffu, sA, o);
            sB += __shfl_xor_sync(0xffffffffu, sB, o);
        }
        if (lane == 0) {
            g_alphaE[rA.y] = 1.f / (1.f + __expf(-(sA + wb)));
            g_alphaE[rB.y] = 1.f / (1.f + __expf(-(sB + wb)));
        }
    }
    if (k < s1) {
        int2 rA = g_eRec[k];
        int bA = rA.x & 511, rrA = rA.x >> 9;
        uint2 vA = V2[rrA * 32 + lane];
        uint2 qA = Q2[bA * 32 + lane];
        float2 va0 = u2f2(vA.x), va1 = u2f2(vA.y);
        float2 qa0 = u2f2(qA.x), qa1 = u2f2(qA.y);
        float sA = fmaxf(u0.x + va0.x + qa0.x, 0.f) * w.x
                 + fmaxf(u0.y + va0.y + qa0.y, 0.f) * w.y
                 + fmaxf(u1.x + va1.x + qa1.x, 0.f) * w.z
                 + fmaxf(u1.y + va1.y + qa1.y, 0.f) * w.w;
        #pragma unroll
        for (int o = 16; o > 0; o >>= 1) sA += __shfl_xor_sync(0xffffffffu, sA, o);
        if (lane == 0) g_alphaE[rA.y] = 1.f / (1.f + __expf(-(sA + wb)));
    }
}

// ---------------- aggregation: warp per tail segment, no U gather ----------------
__global__ __launch_bounds__(256)
void k_agg(const float* __restrict__ hidden, const float* __restrict__ rel, int T) {
    int seg = (blockIdx.x * blockDim.x + threadIdx.x) >> 5;
    int lane = threadIdx.x & 31;
    if (seg >= T) return;
    int s0 = g_segstart[seg];
    int s1 = g_segstart[seg + 1];

    const float4* H4 = (const float4*)hidden;
    const float4* R4 = (const float4*)rel;
    float4 acc = make_float4(0.f, 0.f, 0.f, 0.f);

    int k = s0;
    for (; k + 1 < s1; k += 2) {
        int2 pA = g_aggRec2[k];
        int2 pB = g_aggRec2[k + 1];
        int nA = pA.x & 0x3FFFF, rA = pA.x >> 18;
        int nB = pB.x & 0x3FFFF, rB = pB.x >> 18;
        float aAv = g_alphaE[pA.y];
        float aBv = g_alphaE[pB.y];
        float4 hA = H4[nA * 32 + lane], hB = H4[nB * 32 + lane];
        float4 gA = R4[rA * 32 + lane], gB = R4[rB * 32 + lane];
        acc.x = fmaf(aAv, hA.x + gA.x, acc.x);
        acc.y = fmaf(aAv, hA.y + gA.y, acc.y);
        acc.z = fmaf(aAv, hA.z + gA.z, acc.z);
        acc.w = fmaf(aAv, hA.w + gA.w, acc.w);
        acc.x = fmaf(aBv, hB.x + gB.x, acc.x);
        acc.y = fmaf(aBv, hB.y + gB.y, acc.y);
        acc.z = fmaf(aBv, hB.z + gB.z, acc.z);
        acc.w = fmaf(aBv, hB.w + gB.w, acc.w);
    }
    if (k < s1) {
        int2 pA = g_aggRec2[k];
        int nA = pA.x & 0x3FFFF, rA = pA.x >> 18;
        float aAv = g_alphaE[pA.y];
        float4 hA = H4[nA * 32 + lane];
        float4 gA = R4[rA * 32 + lane];
        acc.x = fmaf(aAv, hA.x + gA.x, acc.x);
        acc.y = fmaf(aAv, hA.y + gA.y, acc.y);
        acc.z = fmaf(aAv, hA.z + gA.z, acc.z);
        acc.w = fmaf(aAv, hA.w + gA.w, acc.w);
    }
    ((float4*)g_AGG)[seg * 32 + lane] = acc;
}

// ---------------- launch ----------------
extern "C" void kernel_launch(void* const* d_in, const int* in_sizes, int n_in,
                              void* d_out, int out_size) {
    const float* hidden    = (const float*)d_in[0];
    const float* rel_table = (const float*)d_in[1];
    const float* Ws        = (const float*)d_in[2];
    const float* Wr        = (const float*)d_in[3];
    const float* Wqr_w     = (const float*)d_in[4];
    const float* Wqr_b     = (const float*)d_in[5];
    const float* wa_w      = (const float*)d_in[6];
    const float* wa_b      = (const float*)d_in[7];
    const float* Wh        = (const float*)d_in[8];
    const int*   query_rel = (const int*)d_in[9];
    const int*   facts     = (const int*)d_in[10];
    const int*   tail      = (const int*)d_in[11];

    const int E  = in_sizes[11];          // 1,000,000
    const int T  = in_sizes[12];          // 100,000
    const int N  = in_sizes[0] / DDIM;    // 200,000
    const int B  = in_sizes[9];           // 512
    const int NR = in_sizes[1] / DDIM;    // 481
    float* out = (float*)d_out;

    // one-time host-side stream/event creation (before first capture; no device mem)
    static cudaStream_t s1 = nullptr, s2 = nullptr;
    static cudaEvent_t evFork = nullptr, evSort = nullptr, evNSort = nullptr;
    if (s1 == nullptr) {
        cudaStreamCreateWithFlags(&s1, cudaStreamNonBlocking);
        cudaStreamCreateWithFlags(&s2, cudaStreamNonBlocking);
        cudaEventCreateWithFlags(&evFork, cudaEventDisableTiming);
        cudaEventCreateWithFlags(&evSort, cudaEventDisableTiming);
        cudaEventCreateWithFlags(&evNSort, cudaEventDisableTiming);
    }

    cudaFuncSetAttribute((const void*)gemm_bf16,
                         cudaFuncAttributeMaxDynamicSharedMemorySize, SMEM_G1);
    cudaFuncSetAttribute((const void*)gemm_mma,
                         cudaFuncAttributeMaxDynamicSharedMemorySize, SMEM_G3);

    float* d_AGG; cudaGetSymbolAddress((void**)&d_AGG, g_AGG);
    uint32_t* d_U16; cudaGetSymbolAddress((void**)&d_U16, g_U16);
    int *d_segcnt, *d_segstart, *d_cursor, *d_part;
    int *d_ncnt, *d_nstart, *d_ncursor, *d_partN;
    cudaGetSymbolAddress((void**)&d_segcnt, g_segcnt);
    cudaGetSymbolAddress((void**)&d_segstart, g_segstart);
    cudaGetSymbolAddress((void**)&d_cursor, g_cursor);
    cudaGetSymbolAddress((void**)&d_part, g_part);
    cudaGetSymbolAddress((void**)&d_ncnt, g_ncnt);
    cudaGetSymbolAddress((void**)&d_nstart, g_nstart);
    cudaGetSymbolAddress((void**)&d_ncursor, g_ncursor);
    cudaGetSymbolAddress((void**)&d_partN, g_partN);
    uint32_t *d_WsHi, *d_WhHi, *d_WhLo;
    cudaGetSymbolAddress((void**)&d_WsHi, g_WsHi);
    cudaGetSymbolAddress((void**)&d_WhHi, g_WhHi);
    cudaGetSymbolAddress((void**)&d_WhLo, g_WhLo);

    int nbT = (T + 1023) / 1024;
    int nbN = (N + 1023) / 1024;

    // fork: s1 = tail sort, s2 = vrqb + node sort, default = prep + GEMM1
    cudaEventRecord(evFork, 0);
    cudaStreamWaitEvent(s1, evFork, 0);
    cudaStreamWaitEvent(s2, evFork, 0);

    // default stream: weight prep + GEMM1 (gemm_bf16 = 4th enqueued launch)
    k_prep_w2<<<2, 128>>>(Ws, Wh);                                               // 0
    k_vrqb<<<NR + B, DDIM, 0, s2>>>(rel_table, Wr, Wqr_w, Wqr_b, query_rel, NR); // 1 (s2)
    k_zero<<<(T + 255) / 256, 256, 0, s1>>>(d_segcnt, T);                        // 2 (s1)
    gemm_bf16<<<(N + 63) / 64, 256, SMEM_G1>>>(hidden, d_WsHi, d_U16, N);        // 3 <- profiled

    // s1: tail sort
    k_hist_tail<<<(E + 255) / 256, 256, 0, s1>>>(tail, E);
    k_scanA<<<nbT, 1024, 0, s1>>>(d_segcnt, d_segstart, d_part, T);
    k_scanB<<<1, 256, 0, s1>>>(d_part, nbT);
    k_scanC<<<nbT, 1024, 0, s1>>>(d_segstart, d_cursor, d_part, T, E);
    k_scatter_tail<<<(E + 255) / 256, 256, 0, s1>>>(tail, facts, E);
    cudaEventRecord(evSort, s1);

    // s2: node sort (independent of tail sort)
    k_zero<<<(N + 255) / 256, 256, 0, s2>>>(d_ncnt, N);
    k_hist_n<<<(E + 255) / 256, 256, 0, s2>>>(facts, E);
    k_scanA<<<nbN, 1024, 0, s2>>>(d_ncnt, d_nstart, d_partN, N);
    k_scanB<<<1, 256, 0, s2>>>(d_partN, nbN);
    k_scanC<<<nbN, 1024, 0, s2>>>(d_nstart, d_ncursor, d_partN, N, E);
    k_scatter_n<<<(E + 255) / 256, 256, 0, s2>>>(facts, E);
    cudaEventRecord(evNSort, s2);

    // gates: need U16 (default, in-order) + Vr16/Qb16/eRec (s2)
    cudaStreamWaitEvent(0, evNSort, 0);
    k_alpha<<<(N + 7) / 8, 256>>>(wa_w, wa_b, N);

    // aggregation: needs alphaE (in-order) + tail sort (s1)
    cudaStreamWaitEvent(0, evSort, 0);
    k_agg<<<(T + 7) / 8, 256>>>(hidden, rel_table, T);

    // output projection (serial — co-run proven harmful)
    gemm_mma<<<(T + 63) / 64, 256, SMEM_G3>>>(d_AGG, d_WhHi, d_WhLo, out, T);
}

// round 15
// speedup vs baseline: 1.1274x; 1.1274x over previous
#include <cuda_runtime.h>
#include <cuda_bf16.h>
#include <cstdint>

// Problem constants (fixed for this dataset instance)
#define EMAX 1000000
#define DDIM 128
#define NMAX 200000
#define BMAX 512
#define NRMAX 481      // 2R+1
#define TMAX 100000

// ---------------- device scratch (static globals; no allocation) ----------------
__device__ uint32_t g_U16[NMAX * 64];     // hidden @ Ws, bf16 packed (2 per uint)
__device__ uint32_t g_Vr16[NRMAX * 64];   // rel_table @ Wr, bf16 packed
__device__ uint32_t g_Qb16[BMAX * 64];    // (rel_table[query_rel+1] @ Wqr_w + b), bf16 packed
__device__ float g_AGG[TMAX * DDIM];      // segment sums
// tail sort
__device__ int   g_segcnt[TMAX];
__device__ int   g_segstart[TMAX + 1];
__device__ int   g_cursor[TMAX];
__device__ int   g_part[256];
__device__ int2  g_aggRec2[EMAX];         // tail-sorted, packed: (n | b<<18, r+1)
// pre-split transposed weight images Wt[n][k] (bf16 hi/lo, packed as uint32 = 2 halves)
__device__ uint32_t g_WsHi[8192];
__device__ uint32_t g_WsLo[8192];
__device__ uint32_t g_WhHi[8192];
__device__ uint32_t g_WhLo[8192];

__device__ __forceinline__ uint32_t smem_u32(const void* p) {
    uint32_t a;
    asm("{ .reg .u64 t; cvta.to.shared.u64 t, %1; cvt.u32.u64 %0, t; }" : "=r"(a) : "l"(p));
    return a;
}
__device__ __forceinline__ uint32_t b2u(__nv_bfloat162 h) { return *reinterpret_cast<uint32_t*>(&h); }
__device__ __forceinline__ float2 u2f2(uint32_t u) {
    return __bfloat1622float2(*reinterpret_cast<__nv_bfloat162*>(&u));
}

__device__ __forceinline__ void ldsm_x4(uint32_t addr, uint32_t& r0, uint32_t& r1,
                                        uint32_t& r2, uint32_t& r3) {
    asm volatile("ldmatrix.sync.aligned.m8n8.x4.shared.b16 {%0,%1,%2,%3}, [%4];"
                 : "=r"(r0), "=r"(r1), "=r"(r2), "=r"(r3) : "r"(addr));
}
__device__ __forceinline__ void mma16816(float* d, const uint32_t* a, const uint32_t* b) {
    asm volatile(
        "mma.sync.aligned.m16n8k16.row.col.f32.bf16.bf16.f32 "
        "{%0,%1,%2,%3}, {%4,%5,%6,%7}, {%8,%9}, {%0,%1,%2,%3};"
        : "+f"(d[0]), "+f"(d[1]), "+f"(d[2]), "+f"(d[3])
        : "r"(a[0]), "r"(a[1]), "r"(a[2]), "r"(a[3]), "r"(b[0]), "r"(b[1]));
}

// ---------------- tail sort kernels ----------------
__global__ void k_zeroT(int T) {
    int i = blockIdx.x * blockDim.x + threadIdx.x;
    if (i < T) g_segcnt[i] = 0;
}

__global__ void k_hist_tail(const int* __restrict__ tail, int E) {
    int e = blockIdx.x * blockDim.x + threadIdx.x;
    if (e < E) atomicAdd(&g_segcnt[tail[e]], 1);
}

__global__ void k_scanA(const int* __restrict__ cnt, int* __restrict__ start,
                        int* __restrict__ part, int T) {
    __shared__ int s[1024];
    int i = blockIdx.x * 1024 + threadIdx.x;
    int v = (i < T) ? cnt[i] : 0;
    s[threadIdx.x] = v;
    __syncthreads();
    for (int off = 1; off < 1024; off <<= 1) {
        int x = (threadIdx.x >= off) ? s[threadIdx.x - off] : 0;
        __syncthreads();
        s[threadIdx.x] += x;
        __syncthreads();
    }
    if (i < T) start[i] = s[threadIdx.x] - v;  // block-local exclusive
    if (threadIdx.x == 1023) part[blockIdx.x] = s[1023];
}

__global__ void k_scanB(int* __restrict__ part, int nb) {
    __shared__ int s[256];
    int i = threadIdx.x;
    int v = (i < nb) ? part[i] : 0;
    s[i] = v;
    __syncthreads();
    for (int off = 1; off < 256; off <<= 1) {
        int x = (i >= off) ? s[i - off] : 0;
        __syncthreads();
        s[i] += x;
        __syncthreads();
    }
    if (i < nb) part[i] = s[i] - v;  // exclusive
}

__global__ void k_scanC(int* __restrict__ start, int* __restrict__ cursor,
                        const int* __restrict__ part, int T, int E) {
    int i = blockIdx.x * 1024 + threadIdx.x;
    if (i < T) {
        int v = start[i] + part[blockIdx.x];
        start[i] = v;
        cursor[i] = v;
    }
    if (i == 0) start[T] = E;
}

// tail scatter: packed (n | b<<18, r+1) record at the sorted position
__global__ void k_scatter_tail(const int* __restrict__ tail, const int* __restrict__ facts, int E) {
    int e = blockIdx.x * blockDim.x + threadIdx.x;
    if (e < E) {
        int2 bn = *(const int2*)(facts + e * 6);      // (b, n)
        int2 hr = *(const int2*)(facts + e * 6 + 2);  // (h, r)
        int p = atomicAdd(&g_cursor[tail[e]], 1);
        g_aggRec2[p] = make_int2(bn.y | (bn.x << 18), hr.y + 1);
    }
}

// ---------------- fused tiny projections (bf16 output): blocks [0,NR) -> Vr16, [NR,NR+B) -> Qb16
__global__ void k_vrqb(const float* __restrict__ rel, const float* __restrict__ Wr,
                       const float* __restrict__ Wq, const float* __restrict__ bias,
                       const int* __restrict__ qrel, int NR) {
    __shared__ float row[DDIM];
    __shared__ float val[DDIM];
    int j = threadIdx.x;
    if ((int)blockIdx.x < NR) {
        int r = blockIdx.x;
        row[j] = rel[r * DDIM + j];
        __syncthreads();
        float s = 0.f;
        #pragma unroll 8
        for (int k = 0; k < DDIM; k++) s = fmaf(row[k], Wr[k * DDIM + j], s);
        val[j] = s;
        __syncthreads();
        if (j < 64) g_Vr16[r * 64 + j] = b2u(__floats2bfloat162_rn(val[2 * j], val[2 * j + 1]));
    } else {
        int b = blockIdx.x - NR;
        int r = qrel[b] + 1;
        row[j] = rel[r * DDIM + j];
        __syncthreads();
        float s = bias[j];
        #pragma unroll 8
        for (int k = 0; k < DDIM; k++) s = fmaf(row[k], Wq[k * DDIM + j], s);
        val[j] = s;
        __syncthreads();
        if (j < 64) g_Qb16[b * 64 + j] = b2u(__floats2bfloat162_rn(val[2 * j], val[2 * j + 1]));
    }
}

// ---------------- weight prep: both weights in one launch (block 0: Ws, block 1: Wh) ----------------
__global__ void k_prep_w2(const float* __restrict__ Ws, const float* __restrict__ Wh) {
    const float* W = (blockIdx.x == 0) ? Ws : Wh;
    uint32_t* outHi = (blockIdx.x == 0) ? g_WsHi : g_WhHi;
    uint32_t* outLo = (blockIdx.x == 0) ? g_WsLo : g_WhLo;
    int n = threadIdx.x;
    #pragma unroll 4
    for (int k = 0; k < 128; k += 2) {
        float w0 = W[(k + 0) * 128 + n];
        float w1 = W[(k + 1) * 128 + n];
        __nv_bfloat162 hi = __floats2bfloat162_rn(w0, w1);
        float l0 = w0 - __bfloat162float(hi.x);
        float l1 = w1 - __bfloat162float(hi.y);
        __nv_bfloat162 lo = __floats2bfloat162_rn(l0, l1);
        outHi[n * 64 + (k >> 1)] = b2u(hi);
        outLo[n * 64 + (k >> 1)] = b2u(lo);
    }
}

#define BSTRIDE 136                       // halves per smem row (272B -> conflict-free ldmatrix)

// ---------------- plain-bf16 GEMM (gate path): U16[M,128] = bf16(A[M,128] @ Ws) ----------------
#define SMEM_G1 (192 * BSTRIDE * 2)       // 52224B -> 4 CTAs/SM

__global__ __launch_bounds__(256)
void gemm_bf16(const float* __restrict__ A, const uint32_t* __restrict__ BHi,
               uint32_t* __restrict__ C16, int M) {
    extern __shared__ __align__(16) uint8_t smraw[];
    __nv_bfloat16* sAhi = (__nv_bfloat16*)smraw;
    __nv_bfloat16* sBhi = sAhi + 64 * BSTRIDE;

    const int tid = threadIdx.x;
    const int w = tid >> 5, lane = tid & 31;
    const int rbase = blockIdx.x * 64;

    const uint4* bh4 = (const uint4*)BHi;
    #pragma unroll
    for (int it = 0; it < 8; it++) {
        int i = it * 256 + tid;
        int n = i >> 4, c = i & 15;
        *(uint4*)(sBhi + n * BSTRIDE + c * 8) = bh4[i];
    }
    const float4* A4 = (const float4*)A;
    #pragma unroll
    for (int it = 0; it < 8; it++) {
        int f = it * 256 + tid;           // 0..2047
        int row = f >> 5, c4 = f & 31;
        int gr = rbase + row;
        float4 v = make_float4(0.f, 0.f, 0.f, 0.f);
        if (gr < M) v = A4[gr * 32 + c4];
        __nv_bfloat162 h01 = __floats2bfloat162_rn(v.x, v.y);
        __nv_bfloat162 h23 = __floats2bfloat162_rn(v.z, v.w);
        *(uint2*)(sAhi + row * BSTRIDE + c4 * 4) = make_uint2(b2u(h01), b2u(h23));
    }
    __syncthreads();

    const int wm = w >> 2, wn = w & 3;
    const int quad = lane >> 3, l = lane & 7;
    const uint32_t aoff0 = (uint32_t)(((wm * 32 + 0  + (quad & 1) * 8 + l) * BSTRIDE + (quad >> 1) * 8) * 2);
    const uint32_t aoff1 = (uint32_t)(((wm * 32 + 16 + (quad & 1) * 8 + l) * BSTRIDE + (quad >> 1) * 8) * 2);
    const uint32_t boff0 = (uint32_t)(((wn * 32 + 0  + (quad >> 1) * 8 + l) * BSTRIDE + (quad & 1) * 8) * 2);
    const uint32_t boff1 = (uint32_t)(((wn * 32 + 16 + (quad >> 1) * 8 + l) * BSTRIDE + (quad & 1) * 8) * 2);
    const uint32_t aHi0 = smem_u32(sAhi) + aoff0, aHi1 = smem_u32(sAhi) + aoff1;
    const uint32_t bHi0 = smem_u32(sBhi) + boff0, bHi1 = smem_u32(sBhi) + boff1;

    float acc[2][4][4];
    #pragma unroll
    for (int i = 0; i < 2; i++)
        #pragma unroll
        for (int j = 0; j < 4; j++)
            #pragma unroll
            for (int q = 0; q < 4; q++) acc[i][j][q] = 0.f;

    #pragma unroll 4
    for (int ks = 0; ks < 8; ks++) {
        const uint32_t ko = (uint32_t)(ks * 32);
        uint32_t ah0[4], ah1[4], bh0[4], bh1[4];
        ldsm_x4(aHi0 + ko, ah0[0], ah0[1], ah0[2], ah0[3]);
        ldsm_x4(aHi1 + ko, ah1[0], ah1[1], ah1[2], ah1[3]);
        ldsm_x4(bHi0 + ko, bh0[0], bh0[1], bh0[2], bh0[3]);
        ldsm_x4(bHi1 + ko, bh1[0], bh1[1], bh1[2], bh1[3]);
        mma16816(acc[0][0], ah0, bh0); mma16816(acc[0][1], ah0, bh0 + 2);
        mma16816(acc[0][2], ah0, bh1); mma16816(acc[0][3], ah0, bh1 + 2);
        mma16816(acc[1][0], ah1, bh0); mma16816(acc[1][1], ah1, bh0 + 2);
        mma16816(acc[1][2], ah1, bh1); mma16816(acc[1][3], ah1, bh1 + 2);
    }

    // epilogue: stage packed bf16 pairs in smem (reuse A tile), then coalesced stores
    __syncthreads();
    uint32_t* stage = (uint32_t*)smraw;   // stride 68 uint32 per row (conflict-free)
    #pragma unroll
    for (int i = 0; i < 2; i++) {
        const int rloc = wm * 32 + i * 16 + (lane >> 2);
        #pragma unroll
        for (int jn = 0; jn < 4; jn++) {
            const int cn = wn * 32 + jn * 8 + (lane & 3) * 2;  // even
            stage[rloc * 68 + (cn >> 1)]       = b2u(__floats2bfloat162_rn(acc[i][jn][0], acc[i][jn][1]));
            stage[(rloc + 8) * 68 + (cn >> 1)] = b2u(__floats2bfloat162_rn(acc[i][jn][2], acc[i][jn][3]));
        }
    }
    __syncthreads();
    const uint2* st2 = (const uint2*)stage;   // row stride 34 uint2
    uint2* C2 = (uint2*)C16;                  // row stride 32 uint2
    #pragma unroll
    for (int it = 0; it < 8; it++) {
        int idx = it * 256 + tid;             // 0..2047
        int row = idx >> 5, c2 = idx & 31;
        int gr = rbase + row;
        if (gr < M) C2[gr * 32 + c2] = st2[row * 34 + c2];
    }
}

// ---------------- bf16x3 GEMM (output path): C[M,128] = A[M,128] @ Wh ----------------
#define SOFF_ALO (64 * BSTRIDE)
#define SOFF_BHI (128 * BSTRIDE)
#define SOFF_BLO (256 * BSTRIDE)
#define SMEM_G3 (384 * BSTRIDE * 2)       // 104448 bytes

__global__ __launch_bounds__(256, 2)
void gemm_mma(const float* __restrict__ A, const uint32_t* __restrict__ BHi,
              const uint32_t* __restrict__ BLo, float* __restrict__ C, int M) {
    extern __shared__ __align__(16) uint8_t smraw[];
    __nv_bfloat16* sAhi = (__nv_bfloat16*)smraw;
    __nv_bfloat16* sAlo = sAhi + SOFF_ALO;
    __nv_bfloat16* sBhi = sAhi + SOFF_BHI;
    __nv_bfloat16* sBlo = sAhi + SOFF_BLO;

    const int tid = threadIdx.x;
    const int w = tid >> 5, lane = tid & 31;
    const int rbase = blockIdx.x * 64;

    const uint4* bh4 = (const uint4*)BHi;
    const uint4* bl4 = (const uint4*)BLo;
    #pragma unroll
    for (int it = 0; it < 16; it++) {
        int i = it * 256 + tid;           // 0..4095
        int j = i & 2047;
        int n = j >> 4, c = j & 15;
        __nv_bfloat16* dst = (i < 2048) ? sBhi : sBlo;
        *(uint4*)(dst + n * BSTRIDE + c * 8) = (i < 2048) ? bh4[j] : bl4[j];
    }
    const float4* A4 = (const float4*)A;
    #pragma unroll
    for (int it = 0; it < 8; it++) {
        int f = it * 256 + tid;           // 0..2047
        int row = f >> 5, c4 = f & 31;
        int gr = rbase + row;
        float4 v = make_float4(0.f, 0.f, 0.f, 0.f);
        if (gr < M) v = A4[gr * 32 + c4];
        __nv_bfloat162 h01 = __floats2bfloat162_rn(v.x, v.y);
        __nv_bfloat162 h23 = __floats2bfloat162_rn(v.z, v.w);
        __nv_bfloat162 l01 = __floats2bfloat162_rn(v.x - __bfloat162float(h01.x),
                                                   v.y - __bfloat162float(h01.y));
        __nv_bfloat162 l23 = __floats2bfloat162_rn(v.z - __bfloat162float(h23.x),
                                                   v.w - __bfloat162float(h23.y));
        *(uint2*)(sAhi + row * BSTRIDE + c4 * 4) = make_uint2(b2u(h01), b2u(h23));
        *(uint2*)(sAlo + row * BSTRIDE + c4 * 4) = make_uint2(b2u(l01), b2u(l23));
    }
    __syncthreads();

    const int wm = w >> 2, wn = w & 3;
    const int quad = lane >> 3, l = lane & 7;
    const uint32_t aoff0 = (uint32_t)(((wm * 32 + 0  + (quad & 1) * 8 + l) * BSTRIDE + (quad >> 1) * 8) * 2);
    const uint32_t aoff1 = (uint32_t)(((wm * 32 + 16 + (quad & 1) * 8 + l) * BSTRIDE + (quad >> 1) * 8) * 2);
    const uint32_t boff0 = (uint32_t)(((wn * 32 + 0  + (quad >> 1) * 8 + l) * BSTRIDE + (quad & 1) * 8) * 2);
    const uint32_t boff1 = (uint32_t)(((wn * 32 + 16 + (quad >> 1) * 8 + l) * BSTRIDE + (quad & 1) * 8) * 2);
    const uint32_t sA = smem_u32(sAhi), sAl = smem_u32(sAlo);
    const uint32_t sB = smem_u32(sBhi), sBl = smem_u32(sBlo);
    const uint32_t aHi0 = sA + aoff0, aHi1 = sA + aoff1;
    const uint32_t aLo0 = sAl + aoff0, aLo1 = sAl + aoff1;
    const uint32_t bHi0 = sB + boff0, bHi1 = sB + boff1;
    const uint32_t bLo0 = sBl + boff0, bLo1 = sBl + boff1;

    float acc[2][4][4];
    #pragma unroll
    for (int i = 0; i < 2; i++)
        #pragma unroll
        for (int j = 0; j < 4; j++)
            #pragma unroll
            for (int q = 0; q < 4; q++) acc[i][j][q] = 0.f;

    #pragma unroll 1
    for (int ks = 0; ks < 8; ks++) {
        const uint32_t ko = (uint32_t)(ks * 32);
        uint32_t ah0[4], ah1[4], al0[4], al1[4];
        uint32_t bh0[4], bh1[4], bl0[4], bl1[4];
        ldsm_x4(aHi0 + ko, ah0[0], ah0[1], ah0[2], ah0[3]);
        ldsm_x4(aHi1 + ko, ah1[0], ah1[1], ah1[2], ah1[3]);
        ldsm_x4(bHi0 + ko, bh0[0], bh0[1], bh0[2], bh0[3]);
        ldsm_x4(bHi1 + ko, bh1[0], bh1[1], bh1[2], bh1[3]);
        ldsm_x4(aLo0 + ko, al0[0], al0[1], al0[2], al0[3]);
        ldsm_x4(aLo1 + ko, al1[0], al1[1], al1[2], al1[3]);
        ldsm_x4(bLo0 + ko, bl0[0], bl0[1], bl0[2], bl0[3]);
        ldsm_x4(bLo1 + ko, bl1[0], bl1[1], bl1[2], bl1[3]);

        mma16816(acc[0][0], ah0, bh0); mma16816(acc[0][1], ah0, bh0 + 2);
        mma16816(acc[0][2], ah0, bh1); mma16816(acc[0][3], ah0, bh1 + 2);
        mma16816(acc[1][0], ah1, bh0); mma16816(acc[1][1], ah1, bh0 + 2);
        mma16816(acc[1][2], ah1, bh1); mma16816(acc[1][3], ah1, bh1 + 2);

        mma16816(acc[0][0], ah0, bl0); mma16816(acc[0][1], ah0, bl0 + 2);
        mma16816(acc[0][2], ah0, bl1); mma16816(acc[0][3], ah0, bl1 + 2);
        mma16816(acc[1][0], ah1, bl0); mma16816(acc[1][1], ah1, bl0 + 2);
        mma16816(acc[1][2], ah1, bl1); mma16816(acc[1][3], ah1, bl1 + 2);

        mma16816(acc[0][0], al0, bh0); mma16816(acc[0][1], al0, bh0 + 2);
        mma16816(acc[0][2], al0, bh1); mma16816(acc[0][3], al0, bh1 + 2);
        mma16816(acc[1][0], al1, bh0); mma16816(acc[1][1], al1, bh0 + 2);
        mma16816(acc[1][2], al1, bh1); mma16816(acc[1][3], al1, bh1 + 2);
    }

    // epilogue: direct float2 stores (measured faster than smem staging here)
    #pragma unroll
    for (int i = 0; i < 2; i++) {
        const int r0 = rbase + wm * 32 + i * 16 + (lane >> 2);
        #pragma unroll
        for (int jn = 0; jn < 4; jn++) {
            const int cn = wn * 32 + jn * 8 + (lane & 3) * 2;
            if (r0 < M)     *(float2*)&C[r0 * 128 + cn]       = make_float2(acc[i][jn][0], acc[i][jn][1]);
            if (r0 + 8 < M) *(float2*)&C[(r0 + 8) * 128 + cn] = make_float2(acc[i][jn][2], acc[i][jn][3]);
        }
    }
}

// ---------------- fused gate+aggregation: warp per tail segment, unroll-4 ----------------
// alpha = sigmoid(wa . relu(U16[n]+Vr16[r]+Qb16[b]) + wa_b); acc += alpha*(H[n]+rel[r])
__device__ __forceinline__ float gate_dot(uint2 u, uint2 v, uint2 q, float4 w) {
    float2 u0 = u2f2(u.x), u1 = u2f2(u.y);
    float2 v0 = u2f2(v.x), v1 = u2f2(v.y);
    float2 q0 = u2f2(q.x), q1 = u2f2(q.y);
    return fmaxf(u0.x + v0.x + q0.x, 0.f) * w.x
         + fmaxf(u0.y + v0.y + q0.y, 0.f) * w.y
         + fmaxf(u1.x + v1.x + q1.x, 0.f) * w.z
         + fmaxf(u1.y + v1.y + q1.y, 0.f) * w.w;
}

__global__ __launch_bounds__(256)
void k_gate_agg(const float* __restrict__ hidden, const float* __restrict__ rel,
                const float* __restrict__ wa_w, const float* __restrict__ wa_b, int T) {
    int seg = (blockIdx.x * blockDim.x + threadIdx.x) >> 5;
    int lane = threadIdx.x & 31;
    if (seg >= T) return;
    int s0 = g_segstart[seg];
    int s1 = g_segstart[seg + 1];

    const float4* H4 = (const float4*)hidden;
    const float4* R4 = (const float4*)rel;
    const uint2* U2 = (const uint2*)g_U16;
    const uint2* V2 = (const uint2*)g_Vr16;
    const uint2* Q2 = (const uint2*)g_Qb16;

    float4 w = ((const float4*)wa_w)[lane];
    float wb = wa_b[0];
    float4 acc = make_float4(0.f, 0.f, 0.f, 0.f);

    int k = s0;
    // unroll by 4: four independent edges in flight (4 shfl chains interleaved)
    for (; k + 3 < s1; k += 4) {
        int2 pA = g_aggRec2[k],     pB = g_aggRec2[k + 1];
        int2 pC = g_aggRec2[k + 2], pD = g_aggRec2[k + 3];
        int nA = pA.x & 0x3FFFF, bA = pA.x >> 18, rA = pA.y;
        int nB = pB.x & 0x3FFFF, bB = pB.x >> 18, rB = pB.y;
        int nC = pC.x & 0x3FFFF, bC = pC.x >> 18, rC = pC.y;
        int nD = pD.x & 0x3FFFF, bD = pD.x >> 18, rD = pD.y;
        uint2 uA = U2[nA * 32 + lane], uB = U2[nB * 32 + lane];
        uint2 uC = U2[nC * 32 + lane], uD = U2[nD * 32 + lane];
        uint2 vA = V2[rA * 32 + lane], vB = V2[rB * 32 + lane];
        uint2 vC = V2[rC * 32 + lane], vD = V2[rD * 32 + lane];
        uint2 qA = Q2[bA * 32 + lane], qB = Q2[bB * 32 + lane];
        uint2 qC = Q2[bC * 32 + lane], qD = Q2[bD * 32 + lane];
        float4 hA = H4[nA * 32 + lane], hB = H4[nB * 32 + lane];
        float4 hC = H4[nC * 32 + lane], hD = H4[nD * 32 + lane];
        float4 gA = R4[rA * 32 + lane], gB = R4[rB * 32 + lane];
        float4 gC = R4[rC * 32 + lane], gD = R4[rD * 32 + lane];

        float sA = gate_dot(uA, vA, qA, w);
        float sB = gate_dot(uB, vB, qB, w);
        float sC = gate_dot(uC, vC, qC, w);
        float sD = gate_dot(uD, vD, qD, w);
        #pragma unroll
        for (int o = 16; o > 0; o >>= 1) {
            sA += __shfl_xor_sync(0xffffffffu, sA, o);
            sB += __shfl_xor_sync(0xffffffffu, sB, o);
            sC += __shfl_xor_sync(0xffffffffu, sC, o);
            sD += __shfl_xor_sync(0xffffffffu, sD, o);
        }
        float aAv = 1.f / (1.f + __expf(-(sA + wb)));
        float aBv = 1.f / (1.f + __expf(-(sB + wb)));
        float aCv = 1.f / (1.f + __expf(-(sC + wb)));
        float aDv = 1.f / (1.f + __expf(-(sD + wb)));
        acc.x = fmaf(aAv, hA.x + gA.x, acc.x);
        acc.y = fmaf(aAv, hA.y + gA.y, acc.y);
        acc.z = fmaf(aAv, hA.z + gA.z, acc.z);
        acc.w = fmaf(aAv, hA.w + gA.w, acc.w);
        acc.x = fmaf(aBv, hB.x + gB.x, acc.x);
        acc.y = fmaf(aBv, hB.y + gB.y, acc.y);
        acc.z = fmaf(aBv, hB.z + gB.z, acc.z);
        acc.w = fmaf(aBv, hB.w + gB.w, acc.w);
        acc.x = fmaf(aCv, hC.x + gC.x, acc.x);
        acc.y = fmaf(aCv, hC.y + gC.y, acc.y);
        acc.z = fmaf(aCv, hC.z + gC.z, acc.z);
        acc.w = fmaf(aCv, hC.w + gC.w, acc.w);
        acc.x = fmaf(aDv, hD.x + gD.x, acc.x);
        acc.y = fmaf(aDv, hD.y + gD.y, acc.y);
        acc.z = fmaf(aDv, hD.z + gD.z, acc.z);
        acc.w = fmaf(aDv, hD.w + gD.w, acc.w);
    }
    // tail: 0..3 remaining edges
    for (; k < s1; k++) {
        int2 pA = g_aggRec2[k];
        int nA = pA.x & 0x3FFFF, bA = pA.x >> 18, rA = pA.y;
        uint2 uA = U2[nA * 32 + lane];
        uint2 vA = V2[rA * 32 + lane];
        uint2 qA = Q2[bA * 32 + lane];
        float4 hA = H4[nA * 32 + lane];
        float4 gA = R4[rA * 32 + lane];
        float sA = gate_dot(uA, vA, qA, w);
        #pragma unroll
        for (int o = 16; o > 0; o >>= 1) sA += __shfl_xor_sync(0xffffffffu, sA, o);
        float aAv = 1.f / (1.f + __expf(-(sA + wb)));
        acc.x = fmaf(aAv, hA.x + gA.x, acc.x);
        acc.y = fmaf(aAv, hA.y + gA.y, acc.y);
        acc.z = fmaf(aAv, hA.z + gA.z, acc.z);
        acc.w = fmaf(aAv, hA.w + gA.w, acc.w);
    }
    ((float4*)g_AGG)[seg * 32 + lane] = acc;
}

// ---------------- launch ----------------
extern "C" void kernel_launch(void* const* d_in, const int* in_sizes, int n_in,
                              void* d_out, int out_size) {
    const float* hidden    = (const float*)d_in[0];
    const float* rel_table = (const float*)d_in[1];
    const float* Ws        = (const float*)d_in[2];
    const float* Wr        = (const float*)d_in[3];
    const float* Wqr_w     = (const float*)d_in[4];
    const float* Wqr_b     = (const float*)d_in[5];
    const float* wa_w      = (const float*)d_in[6];
    const float* wa_b      = (const float*)d_in[7];
    const float* Wh        = (const float*)d_in[8];
    const int*   query_rel = (const int*)d_in[9];
    const int*   facts     = (const int*)d_in[10];
    const int*   tail      = (const int*)d_in[11];

    const int E  = in_sizes[11];          // 1,000,000
    const int T  = in_sizes[12];          // 100,000
    const int N  = in_sizes[0] / DDIM;    // 200,000
    const int B  = in_sizes[9];           // 512
    const int NR = in_sizes[1] / DDIM;    // 481
    float* out = (float*)d_out;

    // one-time host-side stream/event creation (before first capture; no device mem)
    static cudaStream_t s1 = nullptr, s2 = nullptr;
    static cudaEvent_t evFork = nullptr, evSort = nullptr, evVrqb = nullptr;
    if (s1 == nullptr) {
        cudaStreamCreateWithFlags(&s1, cudaStreamNonBlocking);
        cudaStreamCreateWithFlags(&s2, cudaStreamNonBlocking);
        cudaEventCreateWithFlags(&evFork, cudaEventDisableTiming);
        cudaEventCreateWithFlags(&evSort, cudaEventDisableTiming);
        cudaEventCreateWithFlags(&evVrqb, cudaEventDisableTiming);
    }

    cudaFuncSetAttribute((const void*)gemm_bf16,
                         cudaFuncAttributeMaxDynamicSharedMemorySize, SMEM_G1);
    cudaFuncSetAttribute((const void*)gemm_mma,
                         cudaFuncAttributeMaxDynamicSharedMemorySize, SMEM_G3);

    float* d_AGG; cudaGetSymbolAddress((void**)&d_AGG, g_AGG);
    uint32_t* d_U16; cudaGetSymbolAddress((void**)&d_U16, g_U16);
    int *d_segcnt, *d_segstart, *d_cursor, *d_part;
    cudaGetSymbolAddress((void**)&d_segcnt, g_segcnt);
    cudaGetSymbolAddress((void**)&d_segstart, g_segstart);
    cudaGetSymbolAddress((void**)&d_cursor, g_cursor);
    cudaGetSymbolAddress((void**)&d_part, g_part);
    uint32_t *d_WsHi, *d_WhHi, *d_WhLo;
    cudaGetSymbolAddress((void**)&d_WsHi, g_WsHi);
    cudaGetSymbolAddress((void**)&d_WhHi, g_WhHi);
    cudaGetSymbolAddress((void**)&d_WhLo, g_WhLo);

    int nbT = (T + 1023) / 1024;

    // fork: branch B (sort chain) on s1, branch C (vrqb) on s2, branch A (prep+GEMM1) on default
    cudaEventRecord(evFork, 0);
    cudaStreamWaitEvent(s1, evFork, 0);
    cudaStreamWaitEvent(s2, evFork, 0);

    // branch A (default stream): weight prep + GEMM1 (gemm_bf16 = 4th enqueued launch)
    k_prep_w2<<<2, 128>>>(Ws, Wh);                                               // 0
    k_vrqb<<<NR + B, DDIM, 0, s2>>>(rel_table, Wr, Wqr_w, Wqr_b, query_rel, NR); // 1 (s2)
    k_zeroT<<<(T + 255) / 256, 256, 0, s1>>>(T);                                 // 2 (s1)
    gemm_bf16<<<(N + 63) / 64, 256, SMEM_G1>>>(hidden, d_WsHi, d_U16, N);        // 3 <- profiled
    cudaEventRecord(evVrqb, s2);

    // branch B continued (s1): counting sort of edges by tail segment
    k_hist_tail<<<(E + 255) / 256, 256, 0, s1>>>(tail, E);
    k_scanA<<<nbT, 1024, 0, s1>>>(d_segcnt, d_segstart, d_part, T);
    k_scanB<<<1, 256, 0, s1>>>(d_part, nbT);
    k_scanC<<<nbT, 1024, 0, s1>>>(d_segstart, d_cursor, d_part, T, E);
    k_scatter_tail<<<(E + 255) / 256, 256, 0, s1>>>(tail, facts, E);
    cudaEventRecord(evSort, s1);

    // join: gate+agg needs U16 (A), Vr16/Qb16 (C), segstart/aggRec2 (B)
    cudaStreamWaitEvent(0, evSort, 0);
    cudaStreamWaitEvent(0, evVrqb, 0);
    k_gate_agg<<<(T + 7) / 8, 256>>>(hidden, rel_table, wa_w, wa_b, T);

    // output projection (full bf16x3 precision, serial — co-run proven harmful)
    gemm_mma<<<(T + 63) / 64, 256, SMEM_G3>>>(d_AGG, d_WhHi, d_WhLo, out, T);
}

// round 16
// speedup vs baseline: 1.1806x; 1.0472x over previous
#include <cuda_runtime.h>
#include <cuda_bf16.h>
#include <cstdint>

// Problem constants (fixed for this dataset instance)
#define EMAX 1000000
#define DDIM 128
#define NMAX 200000
#define BMAX 512
#define NRMAX 481      // 2R+1
#define TMAX 100000

// ---------------- device scratch (static globals; no allocation) ----------------
__device__ uint32_t g_U16[NMAX * 64];     // hidden @ Ws, bf16 packed (2 per uint)
__device__ uint32_t g_Vr16[NRMAX * 64];   // rel_table @ Wr, bf16 packed
__device__ uint32_t g_Qb16[BMAX * 64];    // (rel_table[query_rel+1] @ Wqr_w + b), bf16 packed
__device__ float g_AGG[TMAX * DDIM];      // segment sums
// tail sort
__device__ int   g_segcnt[TMAX];
__device__ int   g_segstart[TMAX + 1];
__device__ int   g_cursor[TMAX];
__device__ int   g_part[256];
__device__ int2  g_aggRec2[EMAX];         // tail-sorted, packed: (n | b<<18, r+1)
// pre-split transposed weight images Wt[n][k] (bf16 hi/lo, packed as uint32 = 2 halves)
__device__ uint32_t g_WsHi[8192];
__device__ uint32_t g_WsLo[8192];
__device__ uint32_t g_WhHi[8192];
__device__ uint32_t g_WhLo[8192];

__device__ __forceinline__ uint32_t smem_u32(const void* p) {
    uint32_t a;
    asm("{ .reg .u64 t; cvta.to.shared.u64 t, %1; cvt.u32.u64 %0, t; }" : "=r"(a) : "l"(p));
    return a;
}
__device__ __forceinline__ uint32_t b2u(__nv_bfloat162 h) { return *reinterpret_cast<uint32_t*>(&h); }
__device__ __forceinline__ float2 u2f2(uint32_t u) {
    return __bfloat1622float2(*reinterpret_cast<__nv_bfloat162*>(&u));
}

__device__ __forceinline__ void ldsm_x4(uint32_t addr, uint32_t& r0, uint32_t& r1,
                                        uint32_t& r2, uint32_t& r3) {
    asm volatile("ldmatrix.sync.aligned.m8n8.x4.shared.b16 {%0,%1,%2,%3}, [%4];"
                 : "=r"(r0), "=r"(r1), "=r"(r2), "=r"(r3) : "r"(addr));
}
__device__ __forceinline__ void mma16816(float* d, const uint32_t* a, const uint32_t* b) {
    asm volatile(
        "mma.sync.aligned.m16n8k16.row.col.f32.bf16.bf16.f32 "
        "{%0,%1,%2,%3}, {%4,%5,%6,%7}, {%8,%9}, {%0,%1,%2,%3};"
        : "+f"(d[0]), "+f"(d[1]), "+f"(d[2]), "+f"(d[3])
        : "r"(a[0]), "r"(a[1]), "r"(a[2]), "r"(a[3]), "r"(b[0]), "r"(b[1]));
}

// ---------------- tail sort kernels ----------------
__global__ void k_zeroT(int T) {
    int i = blockIdx.x * blockDim.x + threadIdx.x;
    if (i < T) g_segcnt[i] = 0;
}

__global__ void k_hist_tail(const int* __restrict__ tail, int E) {
    int e = blockIdx.x * blockDim.x + threadIdx.x;
    if (e < E) atomicAdd(&g_segcnt[tail[e]], 1);
}

__global__ void k_scanA(const int* __restrict__ cnt, int* __restrict__ start,
                        int* __restrict__ part, int T) {
    __shared__ int s[1024];
    int i = blockIdx.x * 1024 + threadIdx.x;
    int v = (i < T) ? cnt[i] : 0;
    s[threadIdx.x] = v;
    __syncthreads();
    for (int off = 1; off < 1024; off <<= 1) {
        int x = (threadIdx.x >= off) ? s[threadIdx.x - off] : 0;
        __syncthreads();
        s[threadIdx.x] += x;
        __syncthreads();
    }
    if (i < T) start[i] = s[threadIdx.x] - v;  // block-local exclusive
    if (threadIdx.x == 1023) part[blockIdx.x] = s[1023];
}

__global__ void k_scanB(int* __restrict__ part, int nb) {
    __shared__ int s[256];
    int i = threadIdx.x;
    int v = (i < nb) ? part[i] : 0;
    s[i] = v;
    __syncthreads();
    for (int off = 1; off < 256; off <<= 1) {
        int x = (i >= off) ? s[i - off] : 0;
        __syncthreads();
        s[i] += x;
        __syncthreads();
    }
    if (i < nb) part[i] = s[i] - v;  // exclusive
}

__global__ void k_scanC(int* __restrict__ start, int* __restrict__ cursor,
                        const int* __restrict__ part, int T, int E) {
    int i = blockIdx.x * 1024 + threadIdx.x;
    if (i < T) {
        int v = start[i] + part[blockIdx.x];
        start[i] = v;
        cursor[i] = v;
    }
    if (i == 0) start[T] = E;
}

// tail scatter: packed (n | b<<18, r+1) record at the sorted position
__global__ void k_scatter_tail(const int* __restrict__ tail, const int* __restrict__ facts, int E) {
    int e = blockIdx.x * blockDim.x + threadIdx.x;
    if (e < E) {
        int2 bn = *(const int2*)(facts + e * 6);      // (b, n)
        int2 hr = *(const int2*)(facts + e * 6 + 2);  // (h, r)
        int p = atomicAdd(&g_cursor[tail[e]], 1);
        g_aggRec2[p] = make_int2(bn.y | (bn.x << 18), hr.y + 1);
    }
}

// ---------------- fused tiny projections (bf16 output): blocks [0,NR) -> Vr16, [NR,NR+B) -> Qb16
__global__ void k_vrqb(const float* __restrict__ rel, const float* __restrict__ Wr,
                       const float* __restrict__ Wq, const float* __restrict__ bias,
                       const int* __restrict__ qrel, int NR) {
    __shared__ float row[DDIM];
    __shared__ float val[DDIM];
    int j = threadIdx.x;
    if ((int)blockIdx.x < NR) {
        int r = blockIdx.x;
        row[j] = rel[r * DDIM + j];
        __syncthreads();
        float s = 0.f;
        #pragma unroll 8
        for (int k = 0; k < DDIM; k++) s = fmaf(row[k], Wr[k * DDIM + j], s);
        val[j] = s;
        __syncthreads();
        if (j < 64) g_Vr16[r * 64 + j] = b2u(__floats2bfloat162_rn(val[2 * j], val[2 * j + 1]));
    } else {
        int b = blockIdx.x - NR;
        int r = qrel[b] + 1;
        row[j] = rel[r * DDIM + j];
        __syncthreads();
        float s = bias[j];
        #pragma unroll 8
        for (int k = 0; k < DDIM; k++) s = fmaf(row[k], Wq[k * DDIM + j], s);
        val[j] = s;
        __syncthreads();
        if (j < 64) g_Qb16[b * 64 + j] = b2u(__floats2bfloat162_rn(val[2 * j], val[2 * j + 1]));
    }
}

// ---------------- weight prep: both weights in one launch (block 0: Ws, block 1: Wh) ----------------
__global__ void k_prep_w2(const float* __restrict__ Ws, const float* __restrict__ Wh) {
    const float* W = (blockIdx.x == 0) ? Ws : Wh;
    uint32_t* outHi = (blockIdx.x == 0) ? g_WsHi : g_WhHi;
    uint32_t* outLo = (blockIdx.x == 0) ? g_WsLo : g_WhLo;
    int n = threadIdx.x;
    #pragma unroll 4
    for (int k = 0; k < 128; k += 2) {
        float w0 = W[(k + 0) * 128 + n];
        float w1 = W[(k + 1) * 128 + n];
        __nv_bfloat162 hi = __floats2bfloat162_rn(w0, w1);
        float l0 = w0 - __bfloat162float(hi.x);
        float l1 = w1 - __bfloat162float(hi.y);
        __nv_bfloat162 lo = __floats2bfloat162_rn(l0, l1);
        outHi[n * 64 + (k >> 1)] = b2u(hi);
        outLo[n * 64 + (k >> 1)] = b2u(lo);
    }
}

#define BSTRIDE 136                       // halves per smem row (272B -> conflict-free ldmatrix)

// ---------------- plain-bf16 GEMM (gate path): U16[M,128] = bf16(A[M,128] @ Ws) ----------------
#define SMEM_G1 (192 * BSTRIDE * 2)       // 52224B -> 4 CTAs/SM

__global__ __launch_bounds__(256)
void gemm_bf16(const float* __restrict__ A, const uint32_t* __restrict__ BHi,
               uint32_t* __restrict__ C16, int M) {
    extern __shared__ __align__(16) uint8_t smraw[];
    __nv_bfloat16* sAhi = (__nv_bfloat16*)smraw;
    __nv_bfloat16* sBhi = sAhi + 64 * BSTRIDE;

    const int tid = threadIdx.x;
    const int w = tid >> 5, lane = tid & 31;
    const int rbase = blockIdx.x * 64;

    const uint4* bh4 = (const uint4*)BHi;
    #pragma unroll
    for (int it = 0; it < 8; it++) {
        int i = it * 256 + tid;
        int n = i >> 4, c = i & 15;
        *(uint4*)(sBhi + n * BSTRIDE + c * 8) = bh4[i];
    }
    const float4* A4 = (const float4*)A;
    #pragma unroll
    for (int it = 0; it < 8; it++) {
        int f = it * 256 + tid;           // 0..2047
        int row = f >> 5, c4 = f & 31;
        int gr = rbase + row;
        float4 v = make_float4(0.f, 0.f, 0.f, 0.f);
        if (gr < M) v = A4[gr * 32 + c4];
        __nv_bfloat162 h01 = __floats2bfloat162_rn(v.x, v.y);
        __nv_bfloat162 h23 = __floats2bfloat162_rn(v.z, v.w);
        *(uint2*)(sAhi + row * BSTRIDE + c4 * 4) = make_uint2(b2u(h01), b2u(h23));
    }
    __syncthreads();

    const int wm = w >> 2, wn = w & 3;
    const int quad = lane >> 3, l = lane & 7;
    const uint32_t aoff0 = (uint32_t)(((wm * 32 + 0  + (quad & 1) * 8 + l) * BSTRIDE + (quad >> 1) * 8) * 2);
    const uint32_t aoff1 = (uint32_t)(((wm * 32 + 16 + (quad & 1) * 8 + l) * BSTRIDE + (quad >> 1) * 8) * 2);
    const uint32_t boff0 = (uint32_t)(((wn * 32 + 0  + (quad >> 1) * 8 + l) * BSTRIDE + (quad & 1) * 8) * 2);
    const uint32_t boff1 = (uint32_t)(((wn * 32 + 16 + (quad >> 1) * 8 + l) * BSTRIDE + (quad & 1) * 8) * 2);
    const uint32_t aHi0 = smem_u32(sAhi) + aoff0, aHi1 = smem_u32(sAhi) + aoff1;
    const uint32_t bHi0 = smem_u32(sBhi) + boff0, bHi1 = smem_u32(sBhi) + boff1;

    float acc[2][4][4];
    #pragma unroll
    for (int i = 0; i < 2; i++)
        #pragma unroll
        for (int j = 0; j < 4; j++)
            #pragma unroll
            for (int q = 0; q < 4; q++) acc[i][j][q] = 0.f;

    #pragma unroll 4
    for (int ks = 0; ks < 8; ks++) {
        const uint32_t ko = (uint32_t)(ks * 32);
        uint32_t ah0[4], ah1[4], bh0[4], bh1[4];
        ldsm_x4(aHi0 + ko, ah0[0], ah0[1], ah0[2], ah0[3]);
        ldsm_x4(aHi1 + ko, ah1[0], ah1[1], ah1[2], ah1[3]);
        ldsm_x4(bHi0 + ko, bh0[0], bh0[1], bh0[2], bh0[3]);
        ldsm_x4(bHi1 + ko, bh1[0], bh1[1], bh1[2], bh1[3]);
        mma16816(acc[0][0], ah0, bh0); mma16816(acc[0][1], ah0, bh0 + 2);
        mma16816(acc[0][2], ah0, bh1); mma16816(acc[0][3], ah0, bh1 + 2);
        mma16816(acc[1][0], ah1, bh0); mma16816(acc[1][1], ah1, bh0 + 2);
        mma16816(acc[1][2], ah1, bh1); mma16816(acc[1][3], ah1, bh1 + 2);
    }

    // epilogue: stage packed bf16 pairs in smem (reuse A tile), then coalesced stores
    __syncthreads();
    uint32_t* stage = (uint32_t*)smraw;   // stride 68 uint32 per row (conflict-free)
    #pragma unroll
    for (int i = 0; i < 2; i++) {
        const int rloc = wm * 32 + i * 16 + (lane >> 2);
        #pragma unroll
        for (int jn = 0; jn < 4; jn++) {
            const int cn = wn * 32 + jn * 8 + (lane & 3) * 2;  // even
            stage[rloc * 68 + (cn >> 1)]       = b2u(__floats2bfloat162_rn(acc[i][jn][0], acc[i][jn][1]));
            stage[(rloc + 8) * 68 + (cn >> 1)] = b2u(__floats2bfloat162_rn(acc[i][jn][2], acc[i][jn][3]));
        }
    }
    __syncthreads();
    const uint2* st2 = (const uint2*)stage;   // row stride 34 uint2
    uint2* C2 = (uint2*)C16;                  // row stride 32 uint2
    #pragma unroll
    for (int it = 0; it < 8; it++) {
        int idx = it * 256 + tid;             // 0..2047
        int row = idx >> 5, c2 = idx & 31;
        int gr = rbase + row;
        if (gr < M) C2[gr * 32 + c2] = st2[row * 34 + c2];
    }
}

// ---------------- bf16x3 GEMM (output path): C[M,128] = A[M,128] @ Wh ----------------
#define SOFF_ALO (64 * BSTRIDE)
#define SOFF_BHI (128 * BSTRIDE)
#define SOFF_BLO (256 * BSTRIDE)
#define SMEM_G3 (384 * BSTRIDE * 2)       // 104448 bytes

__global__ __launch_bounds__(256, 2)
void gemm_mma(const float* __restrict__ A, const uint32_t* __restrict__ BHi,
              const uint32_t* __restrict__ BLo, float* __restrict__ C, int M) {
    extern __shared__ __align__(16) uint8_t smraw[];
    __nv_bfloat16* sAhi = (__nv_bfloat16*)smraw;
    __nv_bfloat16* sAlo = sAhi + SOFF_ALO;
    __nv_bfloat16* sBhi = sAhi + SOFF_BHI;
    __nv_bfloat16* sBlo = sAhi + SOFF_BLO;

    const int tid = threadIdx.x;
    const int w = tid >> 5, lane = tid & 31;
    const int rbase = blockIdx.x * 64;

    const uint4* bh4 = (const uint4*)BHi;
    const uint4* bl4 = (const uint4*)BLo;
    #pragma unroll
    for (int it = 0; it < 16; it++) {
        int i = it * 256 + tid;           // 0..4095
        int j = i & 2047;
        int n = j >> 4, c = j & 15;
        __nv_bfloat16* dst = (i < 2048) ? sBhi : sBlo;
        *(uint4*)(dst + n * BSTRIDE + c * 8) = (i < 2048) ? bh4[j] : bl4[j];
    }
    const float4* A4 = (const float4*)A;
    #pragma unroll
    for (int it = 0; it < 8; it++) {
        int f = it * 256 + tid;           // 0..2047
        int row = f >> 5, c4 = f & 31;
        int gr = rbase + row;
        float4 v = make_float4(0.f, 0.f, 0.f, 0.f);
        if (gr < M) v = A4[gr * 32 + c4];
        __nv_bfloat162 h01 = __floats2bfloat162_rn(v.x, v.y);
        __nv_bfloat162 h23 = __floats2bfloat162_rn(v.z, v.w);
        __nv_bfloat162 l01 = __floats2bfloat162_rn(v.x - __bfloat162float(h01.x),
                                                   v.y - __bfloat162float(h01.y));
        __nv_bfloat162 l23 = __floats2bfloat162_rn(v.z - __bfloat162float(h23.x),
                                                   v.w - __bfloat162float(h23.y));
        *(uint2*)(sAhi + row * BSTRIDE + c4 * 4) = make_uint2(b2u(h01), b2u(h23));
        *(uint2*)(sAlo + row * BSTRIDE + c4 * 4) = make_uint2(b2u(l01), b2u(l23));
    }
    __syncthreads();

    const int wm = w >> 2, wn = w & 3;
    const int quad = lane >> 3, l = lane & 7;
    const uint32_t aoff0 = (uint32_t)(((wm * 32 + 0  + (quad & 1) * 8 + l) * BSTRIDE + (quad >> 1) * 8) * 2);
    const uint32_t aoff1 = (uint32_t)(((wm * 32 + 16 + (quad & 1) * 8 + l) * BSTRIDE + (quad >> 1) * 8) * 2);
    const uint32_t boff0 = (uint32_t)(((wn * 32 + 0  + (quad >> 1) * 8 + l) * BSTRIDE + (quad & 1) * 8) * 2);
    const uint32_t boff1 = (uint32_t)(((wn * 32 + 16 + (quad >> 1) * 8 + l) * BSTRIDE + (quad & 1) * 8) * 2);
    const uint32_t sA = smem_u32(sAhi), sAl = smem_u32(sAlo);
    const uint32_t sB = smem_u32(sBhi), sBl = smem_u32(sBlo);
    const uint32_t aHi0 = sA + aoff0, aHi1 = sA + aoff1;
    const uint32_t aLo0 = sAl + aoff0, aLo1 = sAl + aoff1;
    const uint32_t bHi0 = sB + boff0, bHi1 = sB + boff1;
    const uint32_t bLo0 = sBl + boff0, bLo1 = sBl + boff1;

    float acc[2][4][4];
    #pragma unroll
    for (int i = 0; i < 2; i++)
        #pragma unroll
        for (int j = 0; j < 4; j++)
            #pragma unroll
            for (int q = 0; q < 4; q++) acc[i][j][q] = 0.f;

    #pragma unroll 1
    for (int ks = 0; ks < 8; ks++) {
        const uint32_t ko = (uint32_t)(ks * 32);
        uint32_t ah0[4], ah1[4], al0[4], al1[4];
        uint32_t bh0[4], bh1[4], bl0[4], bl1[4];
        ldsm_x4(aHi0 + ko, ah0[0], ah0[1], ah0[2], ah0[3]);
        ldsm_x4(aHi1 + ko, ah1[0], ah1[1], ah1[2], ah1[3]);
        ldsm_x4(bHi0 + ko, bh0[0], bh0[1], bh0[2], bh0[3]);
        ldsm_x4(bHi1 + ko, bh1[0], bh1[1], bh1[2], bh1[3]);
        ldsm_x4(aLo0 + ko, al0[0], al0[1], al0[2], al0[3]);
        ldsm_x4(aLo1 + ko, al1[0], al1[1], al1[2], al1[3]);
        ldsm_x4(bLo0 + ko, bl0[0], bl0[1], bl0[2], bl0[3]);
        ldsm_x4(bLo1 + ko, bl1[0], bl1[1], bl1[2], bl1[3]);

        mma16816(acc[0][0], ah0, bh0); mma16816(acc[0][1], ah0, bh0 + 2);
        mma16816(acc[0][2], ah0, bh1); mma16816(acc[0][3], ah0, bh1 + 2);
        mma16816(acc[1][0], ah1, bh0); mma16816(acc[1][1], ah1, bh0 + 2);
        mma16816(acc[1][2], ah1, bh1); mma16816(acc[1][3], ah1, bh1 + 2);

        mma16816(acc[0][0], ah0, bl0); mma16816(acc[0][1], ah0, bl0 + 2);
        mma16816(acc[0][2], ah0, bl1); mma16816(acc[0][3], ah0, bl1 + 2);
        mma16816(acc[1][0], ah1, bl0); mma16816(acc[1][1], ah1, bl0 + 2);
        mma16816(acc[1][2], ah1, bl1); mma16816(acc[1][3], ah1, bl1 + 2);

        mma16816(acc[0][0], al0, bh0); mma16816(acc[0][1], al0, bh0 + 2);
        mma16816(acc[0][2], al0, bh1); mma16816(acc[0][3], al0, bh1 + 2);
        mma16816(acc[1][0], al1, bh0); mma16816(acc[1][1], al1, bh0 + 2);
        mma16816(acc[1][2], al1, bh1); mma16816(acc[1][3], al1, bh1 + 2);
    }

    // epilogue: direct float2 stores (measured faster than smem staging here)
    #pragma unroll
    for (int i = 0; i < 2; i++) {
        const int r0 = rbase + wm * 32 + i * 16 + (lane >> 2);
        #pragma unroll
        for (int jn = 0; jn < 4; jn++) {
            const int cn = wn * 32 + jn * 8 + (lane & 3) * 2;
            if (r0 < M)     *(float2*)&C[r0 * 128 + cn]       = make_float2(acc[i][jn][0], acc[i][jn][1]);
            if (r0 + 8 < M) *(float2*)&C[(r0 + 8) * 128 + cn] = make_float2(acc[i][jn][2], acc[i][jn][3]);
        }
    }
}

// ---------------- fused gate+aggregation: warp per tail segment, unroll-4 + pair tail ----------------
// alpha = sigmoid(wa . relu(U16[n]+Vr16[r]+Qb16[b]) + wa_b); acc += alpha*(H[n]+rel[r])
__device__ __forceinline__ float gate_dot(uint2 u, uint2 v, uint2 q, float4 w) {
    float2 u0 = u2f2(u.x), u1 = u2f2(u.y);
    float2 v0 = u2f2(v.x), v1 = u2f2(v.y);
    float2 q0 = u2f2(q.x), q1 = u2f2(q.y);
    return fmaxf(u0.x + v0.x + q0.x, 0.f) * w.x
         + fmaxf(u0.y + v0.y + q0.y, 0.f) * w.y
         + fmaxf(u1.x + v1.x + q1.x, 0.f) * w.z
         + fmaxf(u1.y + v1.y + q1.y, 0.f) * w.w;
}

__global__ __launch_bounds__(128)
void k_gate_agg(const float* __restrict__ hidden, const float* __restrict__ rel,
                const float* __restrict__ wa_w, const float* __restrict__ wa_b, int T) {
    int seg = (blockIdx.x * blockDim.x + threadIdx.x) >> 5;
    int lane = threadIdx.x & 31;
    if (seg >= T) return;
    int s0 = g_segstart[seg];
    int s1 = g_segstart[seg + 1];

    const float4* H4 = (const float4*)hidden;
    const float4* R4 = (const float4*)rel;
    const uint2* U2 = (const uint2*)g_U16;
    const uint2* V2 = (const uint2*)g_Vr16;
    const uint2* Q2 = (const uint2*)g_Qb16;

    float4 w = ((const float4*)wa_w)[lane];
    float wb = wa_b[0];
    float4 acc = make_float4(0.f, 0.f, 0.f, 0.f);

    int k = s0;
    // unroll by 4: four independent edges in flight (4 shfl chains interleaved)
    for (; k + 3 < s1; k += 4) {
        int2 pA = g_aggRec2[k],     pB = g_aggRec2[k + 1];
        int2 pC = g_aggRec2[k + 2], pD = g_aggRec2[k + 3];
        int nA = pA.x & 0x3FFFF, bA = pA.x >> 18, rA = pA.y;
        int nB = pB.x & 0x3FFFF, bB = pB.x >> 18, rB = pB.y;
        int nC = pC.x & 0x3FFFF, bC = pC.x >> 18, rC = pC.y;
        int nD = pD.x & 0x3FFFF, bD = pD.x >> 18, rD = pD.y;
        uint2 uA = U2[nA * 32 + lane], uB = U2[nB * 32 + lane];
        uint2 uC = U2[nC * 32 + lane], uD = U2[nD * 32 + lane];
        uint2 vA = V2[rA * 32 + lane], vB = V2[rB * 32 + lane];
        uint2 vC = V2[rC * 32 + lane], vD = V2[rD * 32 + lane];
        uint2 qA = Q2[bA * 32 + lane], qB = Q2[bB * 32 + lane];
        uint2 qC = Q2[bC * 32 + lane], qD = Q2[bD * 32 + lane];
        float4 hA = H4[nA * 32 + lane], hB = H4[nB * 32 + lane];
        float4 hC = H4[nC * 32 + lane], hD = H4[nD * 32 + lane];
        float4 gA = R4[rA * 32 + lane], gB = R4[rB * 32 + lane];
        float4 gC = R4[rC * 32 + lane], gD = R4[rD * 32 + lane];

        float sA = gate_dot(uA, vA, qA, w);
        float sB = gate_dot(uB, vB, qB, w);
        float sC = gate_dot(uC, vC, qC, w);
        float sD = gate_dot(uD, vD, qD, w);
        #pragma unroll
        for (int o = 16; o > 0; o >>= 1) {
            sA += __shfl_xor_sync(0xffffffffu, sA, o);
            sB += __shfl_xor_sync(0xffffffffu, sB, o);
            sC += __shfl_xor_sync(0xffffffffu, sC, o);
            sD += __shfl_xor_sync(0xffffffffu, sD, o);
        }
        float aAv = 1.f / (1.f + __expf(-(sA + wb)));
        float aBv = 1.f / (1.f + __expf(-(sB + wb)));
        float aCv = 1.f / (1.f + __expf(-(sC + wb)));
        float aDv = 1.f / (1.f + __expf(-(sD + wb)));
        acc.x = fmaf(aAv, hA.x + gA.x, acc.x);
        acc.y = fmaf(aAv, hA.y + gA.y, acc.y);
        acc.z = fmaf(aAv, hA.z + gA.z, acc.z);
        acc.w = fmaf(aAv, hA.w + gA.w, acc.w);
        acc.x = fmaf(aBv, hB.x + gB.x, acc.x);
        acc.y = fmaf(aBv, hB.y + gB.y, acc.y);
        acc.z = fmaf(aBv, hB.z + gB.z, acc.z);
        acc.w = fmaf(aBv, hB.w + gB.w, acc.w);
        acc.x = fmaf(aCv, hC.x + gC.x, acc.x);
        acc.y = fmaf(aCv, hC.y + gC.y, acc.y);
        acc.z = fmaf(aCv, hC.z + gC.z, acc.z);
        acc.w = fmaf(aCv, hC.w + gC.w, acc.w);
        acc.x = fmaf(aDv, hD.x + gD.x, acc.x);
        acc.y = fmaf(aDv, hD.y + gD.y, acc.y);
        acc.z = fmaf(aDv, hD.z + gD.z, acc.z);
        acc.w = fmaf(aDv, hD.w + gD.w, acc.w);
    }
    // pair tail: 2 edges with interleaved shfl chains
    if (k + 1 < s1) {
        int2 pA = g_aggRec2[k], pB = g_aggRec2[k + 1];
        int nA = pA.x & 0x3FFFF, bA = pA.x >> 18, rA = pA.y;
        int nB = pB.x & 0x3FFFF, bB = pB.x >> 18, rB = pB.y;
        uint2 uA = U2[nA * 32 + lane], uB = U2[nB * 32 + lane];
        uint2 vA = V2[rA * 32 + lane], vB = V2[rB * 32 + lane];
        uint2 qA = Q2[bA * 32 + lane], qB = Q2[bB * 32 + lane];
        float4 hA = H4[nA * 32 + lane], hB = H4[nB * 32 + lane];
        float4 gA = R4[rA * 32 + lane], gB = R4[rB * 32 + lane];
        float sA = gate_dot(uA, vA, qA, w);
        float sB = gate_dot(uB, vB, qB, w);
        #pragma unroll
        for (int o = 16; o > 0; o >>= 1) {
            sA += __shfl_xor_sync(0xffffffffu, sA, o);
            sB += __shfl_xor_sync(0xffffffffu, sB, o);
        }
        float aAv = 1.f / (1.f + __expf(-(sA + wb)));
        float aBv = 1.f / (1.f + __expf(-(sB + wb)));
        acc.x = fmaf(aAv, hA.x + gA.x, acc.x);
        acc.y = fmaf(aAv, hA.y + gA.y, acc.y);
        acc.z = fmaf(aAv, hA.z + gA.z, acc.z);
        acc.w = fmaf(aAv, hA.w + gA.w, acc.w);
        acc.x = fmaf(aBv, hB.x + gB.x, acc.x);
        acc.y = fmaf(aBv, hB.y + gB.y, acc.y);
        acc.z = fmaf(aBv, hB.z + gB.z, acc.z);
        acc.w = fmaf(aBv, hB.w + gB.w, acc.w);
        k += 2;
    }
    // scalar tail: at most 1 edge
    if (k < s1) {
        int2 pA = g_aggRec2[k];
        int nA = pA.x & 0x3FFFF, bA = pA.x >> 18, rA = pA.y;
        uint2 uA = U2[nA * 32 + lane];
        uint2 vA = V2[rA * 32 + lane];
        uint2 qA = Q2[bA * 32 + lane];
        float4 hA = H4[nA * 32 + lane];
        float4 gA = R4[rA * 32 + lane];
        float sA = gate_dot(uA, vA, qA, w);
        #pragma unroll
        for (int o = 16; o > 0; o >>= 1) sA += __shfl_xor_sync(0xffffffffu, sA, o);
        float aAv = 1.f / (1.f + __expf(-(sA + wb)));
        acc.x = fmaf(aAv, hA.x + gA.x, acc.x);
        acc.y = fmaf(aAv, hA.y + gA.y, acc.y);
        acc.z = fmaf(aAv, hA.z + gA.z, acc.z);
        acc.w = fmaf(aAv, hA.w + gA.w, acc.w);
    }
    ((float4*)g_AGG)[seg * 32 + lane] = acc;
}

// ---------------- launch ----------------
extern "C" void kernel_launch(void* const* d_in, const int* in_sizes, int n_in,
                              void* d_out, int out_size) {
    const float* hidden    = (const float*)d_in[0];
    const float* rel_table = (const float*)d_in[1];
    const float* Ws        = (const float*)d_in[2];
    const float* Wr        = (const float*)d_in[3];
    const float* Wqr_w     = (const float*)d_in[4];
    const float* Wqr_b     = (const float*)d_in[5];
    const float* wa_w      = (const float*)d_in[6];
    const float* wa_b      = (const float*)d_in[7];
    const float* Wh        = (const float*)d_in[8];
    const int*   query_rel = (const int*)d_in[9];
    const int*   facts     = (const int*)d_in[10];
    const int*   tail      = (const int*)d_in[11];

    const int E  = in_sizes[11];          // 1,000,000
    const int T  = in_sizes[12];          // 100,000
    const int N  = in_sizes[0] / DDIM;    // 200,000
    const int B  = in_sizes[9];           // 512
    const int NR = in_sizes[1] / DDIM;    // 481
    float* out = (float*)d_out;

    // one-time host-side stream/event creation (before first capture; no device mem)
    static cudaStream_t s1 = nullptr, s2 = nullptr;
    static cudaEvent_t evFork = nullptr, evSort = nullptr, evVrqb = nullptr;
    if (s1 == nullptr) {
        cudaStreamCreateWithFlags(&s1, cudaStreamNonBlocking);
        cudaStreamCreateWithFlags(&s2, cudaStreamNonBlocking);
        cudaEventCreateWithFlags(&evFork, cudaEventDisableTiming);
        cudaEventCreateWithFlags(&evSort, cudaEventDisableTiming);
        cudaEventCreateWithFlags(&evVrqb, cudaEventDisableTiming);
    }

    cudaFuncSetAttribute((const void*)gemm_bf16,
                         cudaFuncAttributeMaxDynamicSharedMemorySize, SMEM_G1);
    cudaFuncSetAttribute((const void*)gemm_mma,
                         cudaFuncAttributeMaxDynamicSharedMemorySize, SMEM_G3);

    float* d_AGG; cudaGetSymbolAddress((void**)&d_AGG, g_AGG);
    uint32_t* d_U16; cudaGetSymbolAddress((void**)&d_U16, g_U16);
    int *d_segcnt, *d_segstart, *d_cursor, *d_part;
    cudaGetSymbolAddress((void**)&d_segcnt, g_segcnt);
    cudaGetSymbolAddress((void**)&d_segstart, g_segstart);
    cudaGetSymbolAddress((void**)&d_cursor, g_cursor);
    cudaGetSymbolAddress((void**)&d_part, g_part);
    uint32_t *d_WsHi, *d_WhHi, *d_WhLo;
    cudaGetSymbolAddress((void**)&d_WsHi, g_WsHi);
    cudaGetSymbolAddress((void**)&d_WhHi, g_WhHi);
    cudaGetSymbolAddress((void**)&d_WhLo, g_WhLo);

    int nbT = (T + 1023) / 1024;

    // fork: branch B (sort chain) on s1, branch C (vrqb) on s2, branch A (prep+GEMM1) on default
    cudaEventRecord(evFork, 0);
    cudaStreamWaitEvent(s1, evFork, 0);
    cudaStreamWaitEvent(s2, evFork, 0);

    // branch A (default stream): weight prep + GEMM1 (gemm_bf16 = 4th enqueued launch)
    k_prep_w2<<<2, 128>>>(Ws, Wh);                                               // 0
    k_vrqb<<<NR + B, DDIM, 0, s2>>>(rel_table, Wr, Wqr_w, Wqr_b, query_rel, NR); // 1 (s2)
    k_zeroT<<<(T + 255) / 256, 256, 0, s1>>>(T);                                 // 2 (s1)
    gemm_bf16<<<(N + 63) / 64, 256, SMEM_G1>>>(hidden, d_WsHi, d_U16, N);        // 3 <- profiled
    cudaEventRecord(evVrqb, s2);

    // branch B continued (s1): counting sort of edges by tail segment
    k_hist_tail<<<(E + 255) / 256, 256, 0, s1>>>(tail, E);
    k_scanA<<<nbT, 1024, 0, s1>>>(d_segcnt, d_segstart, d_part, T);
    k_scanB<<<1, 256, 0, s1>>>(d_part, nbT);
    k_scanC<<<nbT, 1024, 0, s1>>>(d_segstart, d_cursor, d_part, T, E);
    k_scatter_tail<<<(E + 255) / 256, 256, 0, s1>>>(tail, facts, E);
    cudaEventRecord(evSort, s1);

    // join: gate+agg needs U16 (A), Vr16/Qb16 (C), segstart/aggRec2 (B)
    cudaStreamWaitEvent(0, evSort, 0);
    cudaStreamWaitEvent(0, evVrqb, 0);
    k_gate_agg<<<(T + 3) / 4, 128>>>(hidden, rel_table, wa_w, wa_b, T);

    // output projection (full bf16x3 precision, serial — co-run proven harmful)
    gemm_mma<<<(T + 63) / 64, 256, SMEM_G3>>>(d_AGG, d_WhHi, d_WhLo, out, T);
}